// round 1
// baseline (speedup 1.0000x reference)
#include <cuda_runtime.h>
#include <cstdint>

// ---------------------------------------------------------------------------
// Decoder: 6-layer transformer, B=32, T=512, D=512 (H=8, Dh=64), DFF=2048
// fp32 baseline: tiled SGEMM + register flash-attention + fused add+LN
// ---------------------------------------------------------------------------

#define BB   32
#define TT   512
#define HH   8
#define DH   64
#define DD   512
#define DFF  2048
#define LL   6
#define NTOK (BB*TT)          // 16384

// Scratch (device globals; no allocation allowed)
__device__ float g_x  [(size_t)NTOK * DD];    // 32 MB
__device__ float g_qkv[(size_t)NTOK * 3*DD];  // 96 MB
__device__ float g_y  [(size_t)NTOK * DD];    // 32 MB
__device__ float g_h  [(size_t)NTOK * DFF];   // 128 MB

// ---------------------------------------------------------------------------
// Embedding: x = 0.5*(track_emb[tid] + artist_emb[aid]) + pos_emb[t]
// ---------------------------------------------------------------------------
__global__ void embed_kernel(const int* __restrict__ tids, const int* __restrict__ aids,
                             const float* __restrict__ te, const float* __restrict__ ae,
                             const float* __restrict__ pe) {
    int token = blockIdx.x;
    int t = token & (TT - 1);
    int ti = tids[token], ai = aids[token];
    int d = threadIdx.x * 4;
    float4 t4 = *(const float4*)(te + (size_t)ti * DD + d);
    float4 a4 = *(const float4*)(ae + (size_t)ai * DD + d);
    float4 p4 = *(const float4*)(pe + (size_t)t  * DD + d);
    float4 o;
    o.x = 0.5f*(t4.x + a4.x) + p4.x;
    o.y = 0.5f*(t4.y + a4.y) + p4.y;
    o.z = 0.5f*(t4.z + a4.z) + p4.z;
    o.w = 0.5f*(t4.w + a4.w) + p4.w;
    *(float4*)(g_x + (size_t)token * DD + d) = o;
}

// ---------------------------------------------------------------------------
// SGEMM: C[M,N] = A[M,K] @ B[K,N] + bias[N], optional ReLU
// 128x128 tile, BK=16, 256 threads, 8x8 microtile. M,N multiples of 128, K of 16.
// ---------------------------------------------------------------------------
template<bool RELU>
__global__ __launch_bounds__(256, 2)
void gemm_bias(const float* __restrict__ A, const float* __restrict__ B,
               const float* __restrict__ bias, float* __restrict__ C,
               int M, int N, int K) {
    __shared__ float As[16][128];
    __shared__ float Bs[16][128];

    int tid = threadIdx.x;
    int m0 = blockIdx.y * 128, n0 = blockIdx.x * 128;
    int tr = tid >> 4, tc = tid & 15;        // 16x16 thread grid
    int ar = tid >> 2, ak = (tid & 3) << 2;  // A loader: 64 rows x 16 cols (x2)
    int br = tid >> 5, bn = (tid & 31) << 2; // B loader: 8 rows x 128 cols (x2)

    const float* Aptr = A + (size_t)(m0 + ar) * K + ak;
    const float* Bptr = B + (size_t)br * N + n0 + bn;

    float acc[8][8];
#pragma unroll
    for (int i = 0; i < 8; i++)
#pragma unroll
        for (int j = 0; j < 8; j++) acc[i][j] = 0.f;

    for (int k0 = 0; k0 < K; k0 += 16) {
        float4 a0 = *(const float4*)(Aptr + k0);
        float4 a1 = *(const float4*)(Aptr + (size_t)64 * K + k0);
        float4 b0 = *(const float4*)(Bptr + (size_t)k0 * N);
        float4 b1 = *(const float4*)(Bptr + (size_t)(k0 + 8) * N);
        __syncthreads();
        As[ak+0][ar] = a0.x; As[ak+1][ar] = a0.y; As[ak+2][ar] = a0.z; As[ak+3][ar] = a0.w;
        As[ak+0][ar+64] = a1.x; As[ak+1][ar+64] = a1.y; As[ak+2][ar+64] = a1.z; As[ak+3][ar+64] = a1.w;
        *(float4*)&Bs[br][bn]   = b0;
        *(float4*)&Bs[br+8][bn] = b1;
        __syncthreads();
#pragma unroll
        for (int kk = 0; kk < 16; kk++) {
            float a[8], b[8];
            *(float4*)(a)   = *(const float4*)&As[kk][tr*8];
            *(float4*)(a+4) = *(const float4*)&As[kk][tr*8+4];
            *(float4*)(b)   = *(const float4*)&Bs[kk][tc*8];
            *(float4*)(b+4) = *(const float4*)&Bs[kk][tc*8+4];
#pragma unroll
            for (int i = 0; i < 8; i++)
#pragma unroll
                for (int j = 0; j < 8; j++)
                    acc[i][j] = fmaf(a[i], b[j], acc[i][j]);
        }
    }

    float bj[8];
#pragma unroll
    for (int j = 0; j < 8; j++) bj[j] = bias[n0 + tc*8 + j];

#pragma unroll
    for (int i = 0; i < 8; i++) {
        float* Crow = C + (size_t)(m0 + tr*8 + i) * N + n0 + tc*8;
#pragma unroll
        for (int j = 0; j < 8; j++) {
            float v = acc[i][j] + bj[j];
            if (RELU) v = fmaxf(v, 0.f);
            acc[i][j] = v;
        }
        *(float4*)(Crow)     = make_float4(acc[i][0], acc[i][1], acc[i][2], acc[i][3]);
        *(float4*)(Crow + 4) = make_float4(acc[i][4], acc[i][5], acc[i][6], acc[i][7]);
    }
}

// ---------------------------------------------------------------------------
// Attention: flash-style, 1 thread = 1 query row, online softmax.
// qkv layout per token: [H][Dh][3] (reshape order). Exact additive -10000 mask
// (causal AND padding), matching the reference even for all-masked rows.
// grid: (B*H, 2), block: 256 threads (query index = by*256 + tid)
// ---------------------------------------------------------------------------
__global__ __launch_bounds__(256, 1)
void attn_kernel(const float* __restrict__ qkv, const int* __restrict__ track_ids,
                 float* __restrict__ y) {
    __shared__ float Ks[16][64];
    __shared__ float Vs[16][64];
    __shared__ float padf[16];   // 1.0 if key unmasked by padding, else 0.0

    int bh = blockIdx.x;
    int b = bh >> 3, h = bh & 7;
    int q = blockIdx.y * 256 + threadIdx.x;
    int tid = threadIdx.x;

    const float* base = qkv + (size_t)(b * TT) * (3*DD) + h * (DH*3);

    float qreg[64];
    const float* qp = base + (size_t)q * (3*DD);
#pragma unroll
    for (int d = 0; d < 64; d++) qreg[d] = qp[d*3];

    float acc[64];
#pragma unroll
    for (int d = 0; d < 64; d++) acc[d] = 0.f;
    float m = -1e30f, ssum = 0.f;

    for (int t0 = 0; t0 < TT; t0 += 16) {
        __syncthreads();
        // cooperative load of K/V tile (16 keys x 64 dims)
#pragma unroll
        for (int it = 0; it < 4; it++) {
            int e = tid + it * 256;
            int j = e >> 6, d = e & 63;
            const float* kp = base + (size_t)(t0 + j) * (3*DD) + d*3;
            Ks[j][d] = kp[1];
            Vs[j][d] = kp[2];
        }
        if (tid < 16)
            padf[tid] = (track_ids[b * TT + t0 + tid] != 0) ? 1.f : 0.f;
        __syncthreads();

        float s[16];
        float tmax = -1e30f;
#pragma unroll
        for (int j = 0; j < 16; j++) {
            float dot = 0.f;
            const float4* K4 = (const float4*)Ks[j];
#pragma unroll
            for (int d4 = 0; d4 < 16; d4++) {
                float4 kk = K4[d4];
                dot = fmaf(qreg[d4*4+0], kk.x, dot);
                dot = fmaf(qreg[d4*4+1], kk.y, dot);
                dot = fmaf(qreg[d4*4+2], kk.z, dot);
                dot = fmaf(qreg[d4*4+3], kk.w, dot);
            }
            bool ok = ((t0 + j) <= q) && (padf[j] != 0.f);
            float sc = dot * 0.125f + (ok ? 0.f : -10000.f);
            s[j] = sc;
            tmax = fmaxf(tmax, sc);
        }
        float mn = fmaxf(m, tmax);
        float corr = __expf(m - mn);
        ssum *= corr;
#pragma unroll
        for (int d = 0; d < 64; d++) acc[d] *= corr;
#pragma unroll
        for (int j = 0; j < 16; j++) {
            float p = __expf(s[j] - mn);
            ssum += p;
            const float4* V4 = (const float4*)Vs[j];
#pragma unroll
            for (int d4 = 0; d4 < 16; d4++) {
                float4 vv = V4[d4];
                acc[d4*4+0] = fmaf(p, vv.x, acc[d4*4+0]);
                acc[d4*4+1] = fmaf(p, vv.y, acc[d4*4+1]);
                acc[d4*4+2] = fmaf(p, vv.z, acc[d4*4+2]);
                acc[d4*4+3] = fmaf(p, vv.w, acc[d4*4+3]);
            }
        }
        m = mn;
    }

    float inv = 1.f / ssum;
    float* yp = y + (size_t)(b * TT + q) * DD + h * DH;
#pragma unroll
    for (int d4 = 0; d4 < 16; d4++) {
        float4 o;
        o.x = acc[d4*4+0] * inv;
        o.y = acc[d4*4+1] * inv;
        o.z = acc[d4*4+2] * inv;
        o.w = acc[d4*4+3] * inv;
        *(float4*)(yp + d4*4) = o;
    }
}

// ---------------------------------------------------------------------------
// Fused residual + LayerNorm: out = LN(x + y) * g + b. One warp per token.
// ---------------------------------------------------------------------------
__global__ void add_ln_kernel(const float* __restrict__ x, const float* __restrict__ y,
                              const float* __restrict__ g, const float* __restrict__ b,
                              float* __restrict__ out) {
    int token = blockIdx.x * 8 + (threadIdx.x >> 5);
    int lane = threadIdx.x & 31;
    const float4* xr = (const float4*)(x + (size_t)token * DD);
    const float4* yr = (const float4*)(y + (size_t)token * DD);

    float4 v[4];
    float s = 0.f;
#pragma unroll
    for (int c = 0; c < 4; c++) {
        float4 a = xr[lane + 32*c];
        float4 w = yr[lane + 32*c];
        v[c].x = a.x + w.x; v[c].y = a.y + w.y;
        v[c].z = a.z + w.z; v[c].w = a.w + w.w;
        s += v[c].x + v[c].y + v[c].z + v[c].w;
    }
#pragma unroll
    for (int off = 16; off; off >>= 1) s += __shfl_xor_sync(0xffffffffu, s, off);
    float mu = s * (1.f / 512.f);

    float sq = 0.f;
#pragma unroll
    for (int c = 0; c < 4; c++) {
        float dx = v[c].x - mu, dy = v[c].y - mu, dz = v[c].z - mu, dw = v[c].w - mu;
        sq += dx*dx + dy*dy + dz*dz + dw*dw;
    }
#pragma unroll
    for (int off = 16; off; off >>= 1) sq += __shfl_xor_sync(0xffffffffu, sq, off);
    float r = rsqrtf(sq * (1.f / 512.f) + 1e-5f);

    const float4* g4 = (const float4*)g;
    const float4* b4 = (const float4*)b;
    float4* orow = (float4*)(out + (size_t)token * DD);
#pragma unroll
    for (int c = 0; c < 4; c++) {
        int idx = lane + 32*c;
        float4 gg = g4[idx], bb = b4[idx];
        float4 o;
        o.x = (v[c].x - mu) * r * gg.x + bb.x;
        o.y = (v[c].y - mu) * r * gg.y + bb.y;
        o.z = (v[c].z - mu) * r * gg.z + bb.z;
        o.w = (v[c].w - mu) * r * gg.w + bb.w;
        orow[idx] = o;
    }
}

// ---------------------------------------------------------------------------
extern "C" void kernel_launch(void* const* d_in, const int* in_sizes, int n_in,
                              void* d_out, int out_size) {
    const int*   track_ids  = (const int*)  d_in[0];
    const int*   artist_ids = (const int*)  d_in[1];
    const float* track_emb  = (const float*)d_in[2];
    const float* artist_emb = (const float*)d_in[3];
    const float* pos_emb    = (const float*)d_in[4];
    const float* Wqkv       = (const float*)d_in[5];
    const float* bqkv       = (const float*)d_in[6];
    const float* Wff        = (const float*)d_in[7];
    const float* bff        = (const float*)d_in[8];
    const float* Wout       = (const float*)d_in[9];
    const float* bout       = (const float*)d_in[10];
    const float* g1         = (const float*)d_in[11];
    const float* b1         = (const float*)d_in[12];
    const float* g2         = (const float*)d_in[13];
    const float* b2         = (const float*)d_in[14];
    float* out = (float*)d_out;

    float *x, *qkv, *y, *h;
    cudaGetSymbolAddress((void**)&x,   g_x);
    cudaGetSymbolAddress((void**)&qkv, g_qkv);
    cudaGetSymbolAddress((void**)&y,   g_y);
    cudaGetSymbolAddress((void**)&h,   g_h);

    embed_kernel<<<NTOK, 128>>>(track_ids, artist_ids, track_emb, artist_emb, pos_emb);

    for (int i = 0; i < LL; i++) {
        // QKV projection: [16384,512] x [512,1536]
        gemm_bias<false><<<dim3((3*DD)/128, NTOK/128), 256>>>(
            x, Wqkv + (size_t)i * DD * (3*DD), bqkv + (size_t)i * (3*DD), qkv,
            NTOK, 3*DD, DD);
        // Attention
        attn_kernel<<<dim3(BB*HH, 2), 256>>>(qkv, track_ids, y);
        // x = LN(x + attn)
        add_ln_kernel<<<NTOK/8, 256>>>(x, y, g1 + (size_t)i*DD, b1 + (size_t)i*DD, x);
        // FF1 (+ReLU): [16384,512] x [512,2048]
        gemm_bias<true><<<dim3(DFF/128, NTOK/128), 256>>>(
            x, Wff + (size_t)i * DD * DFF, bff + (size_t)i * DFF, h,
            NTOK, DFF, DD);
        // FF2: [16384,2048] x [2048,512]
        gemm_bias<false><<<dim3(DD/128, NTOK/128), 256>>>(
            h, Wout + (size_t)i * DFF * DD, bout + (size_t)i * DD, y,
            NTOK, DD, DFF);
        // x = LN(x + ff)  (last layer writes straight to output)
        add_ln_kernel<<<NTOK/8, 256>>>(x, y, g2 + (size_t)i*DD, b2 + (size_t)i*DD,
                                       (i == LL-1) ? out : x);
    }
}

// round 2
// speedup vs baseline: 2.2630x; 2.2630x over previous
#include <cuda_runtime.h>
#include <cstdint>

// ---------------------------------------------------------------------------
// Decoder: 6-layer transformer, B=32, T=512, D=512 (H=8, Dh=64), DFF=2048
// Round 1: tf32 mma.sync GEMMs + planar QKV + causal-skip flash attention
// ---------------------------------------------------------------------------

#define BB   32
#define TT   512
#define HH   8
#define DH   64
#define DD   512
#define DFF  2048
#define LL   6
#define NTOK (BB*TT)          // 16384
#define PLANE ((size_t)NTOK * DD)

// Scratch (device globals; no allocation allowed)
__device__ float g_x  [(size_t)NTOK * DD];    // 32 MB
__device__ float g_qkv[(size_t)NTOK * 3*DD];  // 96 MB (3 planar [B,H,T,Dh] tensors)
__device__ float g_y  [(size_t)NTOK * DD];    // 32 MB
__device__ float g_h  [(size_t)NTOK * DFF];   // 128 MB

__device__ __forceinline__ uint32_t f2tf32(float f) {
    uint32_t u;
    asm("cvt.rna.tf32.f32 %0, %1;" : "=r"(u) : "f"(f));
    return u;
}

__device__ __forceinline__ void mma8(float* c, const uint32_t* a, uint32_t b0, uint32_t b1) {
    asm volatile(
        "mma.sync.aligned.m16n8k8.row.col.f32.tf32.tf32.f32 "
        "{%0,%1,%2,%3}, {%4,%5,%6,%7}, {%8,%9}, {%0,%1,%2,%3};"
        : "+f"(c[0]), "+f"(c[1]), "+f"(c[2]), "+f"(c[3])
        : "r"(a[0]), "r"(a[1]), "r"(a[2]), "r"(a[3]), "r"(b0), "r"(b1));
}

// ---------------------------------------------------------------------------
// Embedding: x = 0.5*(track_emb[tid] + artist_emb[aid]) + pos_emb[t]
// ---------------------------------------------------------------------------
__global__ void embed_kernel(const int* __restrict__ tids, const int* __restrict__ aids,
                             const float* __restrict__ te, const float* __restrict__ ae,
                             const float* __restrict__ pe) {
    int token = blockIdx.x;
    int t = token & (TT - 1);
    int ti = tids[token], ai = aids[token];
    int d = threadIdx.x * 4;
    float4 t4 = *(const float4*)(te + (size_t)ti * DD + d);
    float4 a4 = *(const float4*)(ae + (size_t)ai * DD + d);
    float4 p4 = *(const float4*)(pe + (size_t)t  * DD + d);
    float4 o;
    o.x = 0.5f*(t4.x + a4.x) + p4.x;
    o.y = 0.5f*(t4.y + a4.y) + p4.y;
    o.z = 0.5f*(t4.z + a4.z) + p4.z;
    o.w = 0.5f*(t4.w + a4.w) + p4.w;
    *(float4*)(g_x + (size_t)token * DD + d) = o;
}

// ---------------------------------------------------------------------------
// tf32 tensor-core GEMM: C[M,N] = A[M,K] @ B[K,N] + bias[N]
// 128x128 tile, BK=32, 256 threads (8 warps, warp tile 32x64), m16n8k8 mma.
// MODE: 0 = plain, 1 = ReLU, 2 = QKV scatter to planar [3][B,H,T,Dh]
// ---------------------------------------------------------------------------
template<int MODE>
__global__ __launch_bounds__(256, 2)
void gemm_tf32(const float* __restrict__ A, const float* __restrict__ B,
               const float* __restrict__ bias, float* __restrict__ C,
               int M, int N, int K) {
    __shared__ uint32_t As[128][36];   // padded: conflict-free frag loads
    __shared__ uint32_t Bs[32][136];

    int tid = threadIdx.x;
    int wid = tid >> 5, lane = tid & 31;
    int g = lane >> 2, tc = lane & 3;
    int wm0 = (wid & 3) * 32, wn0 = (wid >> 2) * 64;
    int m0 = blockIdx.y * 128, n0 = blockIdx.x * 128;

    int arow = tid >> 3, ac4 = (tid & 7) * 4;   // A loader
    int brow = tid >> 5, bc4 = (tid & 31) * 4;  // B loader

    float acc[2][8][4];
#pragma unroll
    for (int mf = 0; mf < 2; mf++)
#pragma unroll
        for (int nf = 0; nf < 8; nf++)
#pragma unroll
            for (int e = 0; e < 4; e++) acc[mf][nf][e] = 0.f;

    for (int k0 = 0; k0 < K; k0 += 32) {
        float4 av[4], bv[4];
#pragma unroll
        for (int it = 0; it < 4; it++)
            av[it] = *(const float4*)(A + (size_t)(m0 + arow + 32*it) * K + k0 + ac4);
#pragma unroll
        for (int it = 0; it < 4; it++)
            bv[it] = *(const float4*)(B + (size_t)(k0 + brow + 8*it) * N + n0 + bc4);
        __syncthreads();
#pragma unroll
        for (int it = 0; it < 4; it++) {
            uint32_t* p = &As[arow + 32*it][ac4];
            p[0] = f2tf32(av[it].x); p[1] = f2tf32(av[it].y);
            p[2] = f2tf32(av[it].z); p[3] = f2tf32(av[it].w);
        }
#pragma unroll
        for (int it = 0; it < 4; it++) {
            uint32_t* p = &Bs[brow + 8*it][bc4];
            p[0] = f2tf32(bv[it].x); p[1] = f2tf32(bv[it].y);
            p[2] = f2tf32(bv[it].z); p[3] = f2tf32(bv[it].w);
        }
        __syncthreads();
#pragma unroll
        for (int ks = 0; ks < 4; ks++) {
            int kk = ks * 8;
            uint32_t a[2][4];
#pragma unroll
            for (int mf = 0; mf < 2; mf++) {
                int r = wm0 + mf*16 + g;
                a[mf][0] = As[r][kk + tc];
                a[mf][1] = As[r + 8][kk + tc];
                a[mf][2] = As[r][kk + tc + 4];
                a[mf][3] = As[r + 8][kk + tc + 4];
            }
#pragma unroll
            for (int nf = 0; nf < 8; nf++) {
                int cn = wn0 + nf*8 + g;
                uint32_t b0 = Bs[kk + tc][cn];
                uint32_t b1 = Bs[kk + tc + 4][cn];
                mma8(acc[0][nf], a[0], b0, b1);
                mma8(acc[1][nf], a[1], b0, b1);
            }
        }
    }

    // ---- epilogue ----
#pragma unroll
    for (int mf = 0; mf < 2; mf++) {
#pragma unroll
        for (int half = 0; half < 2; half++) {
            int row = m0 + wm0 + mf*16 + g + half*8;
#pragma unroll
            for (int nf = 0; nf < 8; nf++) {
                int col = n0 + wn0 + nf*8 + tc*2;
                float v0 = acc[mf][nf][half*2 + 0] + bias[col];
                float v1 = acc[mf][nf][half*2 + 1] + bias[col + 1];
                if (MODE == 1) { v0 = fmaxf(v0, 0.f); v1 = fmaxf(v1, 0.f); }
                if (MODE == 2) {
                    // n -> (h, dh, which): reshape(H, Dh, 3)
                    int b = row >> 9, t = row & 511;
#pragma unroll
                    for (int e = 0; e < 2; e++) {
                        int n = col + e;
                        float v = e ? v1 : v0;
                        int h  = n / 192;
                        int r  = n - h * 192;
                        int dh = r / 3;
                        int wh = r - dh * 3;
                        C[(size_t)wh * PLANE + (((size_t)(b*HH + h))*TT + t)*DH + dh] = v;
                    }
                } else {
                    *(float2*)(C + (size_t)row * N + col) = make_float2(v0, v1);
                }
            }
        }
    }
}

// ---------------------------------------------------------------------------
// Attention: planar Q/K/V [B,H,T,Dh], 1 thread = 1 query, online softmax.
// Causal tile skip (exact: skipped terms underflow to 0 in fp32) with
// fallback for fully-padding-masked prefixes (m <= -5000).
// grid: (B*H, 4), block: 128
// ---------------------------------------------------------------------------
__global__ __launch_bounds__(128)
void attn_kernel(const float* __restrict__ qkv, const int* __restrict__ track_ids,
                 float* __restrict__ y) {
    __shared__ float Ks[16][64];
    __shared__ float Vs[16][64];
    __shared__ float padf[16];

    int bh = blockIdx.x;
    int b = bh >> 3, h = bh & 7;
    int q = blockIdx.y * 128 + threadIdx.x;
    int tid = threadIdx.x;

    const float* qpl = qkv;
    const float* kpl = qkv + PLANE;
    const float* vpl = qkv + 2 * PLANE;
    size_t hb = ((size_t)(b*HH + h)) * TT * DH;

    float qreg[64];
#pragma unroll
    for (int d4 = 0; d4 < 16; d4++) {
        float4 v = *(const float4*)(qpl + hb + (size_t)q * DH + d4*4);
        qreg[d4*4+0] = v.x; qreg[d4*4+1] = v.y;
        qreg[d4*4+2] = v.z; qreg[d4*4+3] = v.w;
    }

    float acc[64];
#pragma unroll
    for (int d = 0; d < 64; d++) acc[d] = 0.f;
    float m = -1e30f, ssum = 0.f;

    int nt = (blockIdx.y + 1) * 128;
    int qw = q | 31;   // warp-uniform max query in this warp

    for (int t0 = 0; t0 < TT; t0 += 16) {
        if (t0 >= nt) {
            if (__syncthreads_and(m > -5000.f)) break;   // all done: rest underflows
        }
        __syncthreads();
#pragma unroll
        for (int it = 0; it < 2; it++) {
            int e = tid + it * 128;
            int j = e >> 4, c4 = e & 15;
            ((float4*)&Ks[j][0])[c4] = *(const float4*)(kpl + hb + (size_t)(t0 + j)*DH + c4*4);
            ((float4*)&Vs[j][0])[c4] = *(const float4*)(vpl + hb + (size_t)(t0 + j)*DH + c4*4);
        }
        if (tid < 16)
            padf[tid] = (track_ids[b * TT + t0 + tid] != 0) ? 1.f : 0.f;
        __syncthreads();

        if (t0 <= qw || m <= -5000.f) {
            float s[16];
            float tmax = -1e30f;
#pragma unroll
            for (int j = 0; j < 16; j++) {
                float dot = 0.f;
                const float4* K4 = (const float4*)Ks[j];
#pragma unroll
                for (int d4 = 0; d4 < 16; d4++) {
                    float4 kk = K4[d4];
                    dot = fmaf(qreg[d4*4+0], kk.x, dot);
                    dot = fmaf(qreg[d4*4+1], kk.y, dot);
                    dot = fmaf(qreg[d4*4+2], kk.z, dot);
                    dot = fmaf(qreg[d4*4+3], kk.w, dot);
                }
                bool ok = ((t0 + j) <= q) && (padf[j] != 0.f);
                float sc = dot * 0.125f + (ok ? 0.f : -10000.f);
                s[j] = sc;
                tmax = fmaxf(tmax, sc);
            }
            float mn = fmaxf(m, tmax);
            float corr = __expf(m - mn);
            ssum *= corr;
#pragma unroll
            for (int d = 0; d < 64; d++) acc[d] *= corr;
#pragma unroll
            for (int j = 0; j < 16; j++) {
                float p = __expf(s[j] - mn);
                ssum += p;
                const float4* V4 = (const float4*)Vs[j];
#pragma unroll
                for (int d4 = 0; d4 < 16; d4++) {
                    float4 vv = V4[d4];
                    acc[d4*4+0] = fmaf(p, vv.x, acc[d4*4+0]);
                    acc[d4*4+1] = fmaf(p, vv.y, acc[d4*4+1]);
                    acc[d4*4+2] = fmaf(p, vv.z, acc[d4*4+2]);
                    acc[d4*4+3] = fmaf(p, vv.w, acc[d4*4+3]);
                }
            }
            m = mn;
        }
    }

    float inv = 1.f / ssum;
    float* yp = y + (size_t)(b * TT + q) * DD + h * DH;
#pragma unroll
    for (int d4 = 0; d4 < 16; d4++) {
        float4 o;
        o.x = acc[d4*4+0] * inv;
        o.y = acc[d4*4+1] * inv;
        o.z = acc[d4*4+2] * inv;
        o.w = acc[d4*4+3] * inv;
        *(float4*)(yp + d4*4) = o;
    }
}

// ---------------------------------------------------------------------------
// Fused residual + LayerNorm: out = LN(x + y) * g + b. One warp per token.
// ---------------------------------------------------------------------------
__global__ void add_ln_kernel(const float* __restrict__ x, const float* __restrict__ y,
                              const float* __restrict__ g, const float* __restrict__ b,
                              float* __restrict__ out) {
    int token = blockIdx.x * 8 + (threadIdx.x >> 5);
    int lane = threadIdx.x & 31;
    const float4* xr = (const float4*)(x + (size_t)token * DD);
    const float4* yr = (const float4*)(y + (size_t)token * DD);

    float4 v[4];
    float s = 0.f;
#pragma unroll
    for (int c = 0; c < 4; c++) {
        float4 a = xr[lane + 32*c];
        float4 w = yr[lane + 32*c];
        v[c].x = a.x + w.x; v[c].y = a.y + w.y;
        v[c].z = a.z + w.z; v[c].w = a.w + w.w;
        s += v[c].x + v[c].y + v[c].z + v[c].w;
    }
#pragma unroll
    for (int off = 16; off; off >>= 1) s += __shfl_xor_sync(0xffffffffu, s, off);
    float mu = s * (1.f / 512.f);

    float sq = 0.f;
#pragma unroll
    for (int c = 0; c < 4; c++) {
        float dx = v[c].x - mu, dy = v[c].y - mu, dz = v[c].z - mu, dw = v[c].w - mu;
        sq += dx*dx + dy*dy + dz*dz + dw*dw;
    }
#pragma unroll
    for (int off = 16; off; off >>= 1) sq += __shfl_xor_sync(0xffffffffu, sq, off);
    float r = rsqrtf(sq * (1.f / 512.f) + 1e-5f);

    const float4* g4 = (const float4*)g;
    const float4* b4 = (const float4*)b;
    float4* orow = (float4*)(out + (size_t)token * DD);
#pragma unroll
    for (int c = 0; c < 4; c++) {
        int idx = lane + 32*c;
        float4 gg = g4[idx], bb = b4[idx];
        float4 o;
        o.x = (v[c].x - mu) * r * gg.x + bb.x;
        o.y = (v[c].y - mu) * r * gg.y + bb.y;
        o.z = (v[c].z - mu) * r * gg.z + bb.z;
        o.w = (v[c].w - mu) * r * gg.w + bb.w;
        orow[idx] = o;
    }
}

// ---------------------------------------------------------------------------
extern "C" void kernel_launch(void* const* d_in, const int* in_sizes, int n_in,
                              void* d_out, int out_size) {
    const int*   track_ids  = (const int*)  d_in[0];
    const int*   artist_ids = (const int*)  d_in[1];
    const float* track_emb  = (const float*)d_in[2];
    const float* artist_emb = (const float*)d_in[3];
    const float* pos_emb    = (const float*)d_in[4];
    const float* Wqkv       = (const float*)d_in[5];
    const float* bqkv       = (const float*)d_in[6];
    const float* Wff        = (const float*)d_in[7];
    const float* bff        = (const float*)d_in[8];
    const float* Wout       = (const float*)d_in[9];
    const float* bout       = (const float*)d_in[10];
    const float* g1         = (const float*)d_in[11];
    const float* b1         = (const float*)d_in[12];
    const float* g2         = (const float*)d_in[13];
    const float* b2         = (const float*)d_in[14];
    float* out = (float*)d_out;

    float *x, *qkv, *y, *h;
    cudaGetSymbolAddress((void**)&x,   g_x);
    cudaGetSymbolAddress((void**)&qkv, g_qkv);
    cudaGetSymbolAddress((void**)&y,   g_y);
    cudaGetSymbolAddress((void**)&h,   g_h);

    embed_kernel<<<NTOK, 128>>>(track_ids, artist_ids, track_emb, artist_emb, pos_emb);

    for (int i = 0; i < LL; i++) {
        // QKV projection + planar scatter: [16384,512] x [512,1536]
        gemm_tf32<2><<<dim3((3*DD)/128, NTOK/128), 256>>>(
            x, Wqkv + (size_t)i * DD * (3*DD), bqkv + (size_t)i * (3*DD), qkv,
            NTOK, 3*DD, DD);
        // Attention
        attn_kernel<<<dim3(BB*HH, 4), 128>>>(qkv, track_ids, y);
        // x = LN(x + attn)
        add_ln_kernel<<<NTOK/8, 256>>>(x, y, g1 + (size_t)i*DD, b1 + (size_t)i*DD, x);
        // FF1 (+ReLU): [16384,512] x [512,2048]
        gemm_tf32<1><<<dim3(DFF/128, NTOK/128), 256>>>(
            x, Wff + (size_t)i * DD * DFF, bff + (size_t)i * DFF, h,
            NTOK, DFF, DD);
        // FF2: [16384,2048] x [2048,512]
        gemm_tf32<0><<<dim3(DD/128, NTOK/128), 256>>>(
            h, Wout + (size_t)i * DFF * DD, bout + (size_t)i * DD, y,
            NTOK, DD, DFF);
        // x = LN(x + ff)  (last layer writes straight to output)
        add_ln_kernel<<<NTOK/8, 256>>>(x, y, g2 + (size_t)i*DD, b2 + (size_t)i*DD,
                                       (i == LL-1) ? out : x);
    }
}

// round 3
// speedup vs baseline: 2.4257x; 1.0719x over previous
#include <cuda_runtime.h>
#include <cstdint>

// ---------------------------------------------------------------------------
// Decoder: 6-layer transformer, B=32, T=512, D=512 (H=8, Dh=64), DFF=2048
// Round 2: pipelined double-buffered tf32 GEMMs + pre-permuted QKV weights
// ---------------------------------------------------------------------------

#define BB   32
#define TT   512
#define HH   8
#define DH   64
#define DD   512
#define DFF  2048
#define LL   6
#define NTOK (BB*TT)          // 16384
#define PLANE ((size_t)NTOK * DD)

// Scratch (device globals; no allocation allowed)
__device__ float g_x  [(size_t)NTOK * DD];    // 32 MB
__device__ float g_qkv[(size_t)NTOK * 3*DD];  // 96 MB (3 planar [B,H,T,Dh] tensors)
__device__ float g_y  [(size_t)NTOK * DD];    // 32 MB
__device__ float g_h  [(size_t)NTOK * DFF];   // 128 MB
__device__ float g_wp [(size_t)DD * 3*DD];    // 3 MB permuted Wqkv
__device__ float g_bp [3*DD];                 // permuted bqkv

__device__ __forceinline__ uint32_t f2tf32(float f) {
    uint32_t u;
    asm("cvt.rna.tf32.f32 %0, %1;" : "=r"(u) : "f"(f));
    return u;
}

__device__ __forceinline__ void mma8(float* c, const uint32_t* a, uint32_t b0, uint32_t b1) {
    asm volatile(
        "mma.sync.aligned.m16n8k8.row.col.f32.tf32.tf32.f32 "
        "{%0,%1,%2,%3}, {%4,%5,%6,%7}, {%8,%9}, {%0,%1,%2,%3};"
        : "+f"(c[0]), "+f"(c[1]), "+f"(c[2]), "+f"(c[3])
        : "r"(a[0]), "r"(a[1]), "r"(a[2]), "r"(a[3]), "r"(b0), "r"(b1));
}

// ---------------------------------------------------------------------------
// Embedding
// ---------------------------------------------------------------------------
__global__ void embed_kernel(const int* __restrict__ tids, const int* __restrict__ aids,
                             const float* __restrict__ te, const float* __restrict__ ae,
                             const float* __restrict__ pe) {
    int token = blockIdx.x;
    int t = token & (TT - 1);
    int ti = tids[token], ai = aids[token];
    int d = threadIdx.x * 4;
    float4 t4 = *(const float4*)(te + (size_t)ti * DD + d);
    float4 a4 = *(const float4*)(ae + (size_t)ai * DD + d);
    float4 p4 = *(const float4*)(pe + (size_t)t  * DD + d);
    float4 o;
    o.x = 0.5f*(t4.x + a4.x) + p4.x;
    o.y = 0.5f*(t4.y + a4.y) + p4.y;
    o.z = 0.5f*(t4.z + a4.z) + p4.z;
    o.w = 0.5f*(t4.w + a4.w) + p4.w;
    *(float4*)(g_x + (size_t)token * DD + d) = o;
}

// ---------------------------------------------------------------------------
// Permute Wqkv columns so GEMM output is planar [3][H][Dh] instead of
// interleaved [H][Dh][3]. new col n' = wh*512 + h*64 + dh  <-  orig h*192+dh*3+wh
// grid (6, 512), block 256
// ---------------------------------------------------------------------------
__global__ void permute_wqkv(const float* __restrict__ W, const float* __restrict__ bias) {
    int n = blockIdx.x * 256 + threadIdx.x;       // 0..1535 (new col)
    int k = blockIdx.y;                           // 0..511
    int wh = n >> 9, rem = n & 511;
    int h = rem >> 6, dh = rem & 63;
    int o = h * 192 + dh * 3 + wh;
    g_wp[(size_t)k * (3*DD) + n] = W[(size_t)k * (3*DD) + o];
    if (k == 0) g_bp[n] = bias[o];
}

// ---------------------------------------------------------------------------
// tf32 tensor-core GEMM: C[M,N] = A[M,K] @ B[K,N] + bias[N]
// 128x128 tile, BK=32, 256 threads (8 warps, warp tile 32x64), m16n8k8 mma.
// Software pipeline: LDG(next)->regs ; MMA(cur) ; STS(next) ; sync (1/iter).
// MODE: 0 = plain, 1 = ReLU, 2 = planar QKV output (cols already permuted)
// ---------------------------------------------------------------------------
#define AS_W 4608              // 128*36 words
#define BS_W 4352              // 32*136 words
#define BUF_W (AS_W + BS_W)    // 8960 words per stage
#define GEMM_SMEM (2 * BUF_W * 4)

template<int MODE>
__global__ __launch_bounds__(256, 2)
void gemm_tf32(const float* __restrict__ A, const float* __restrict__ B,
               const float* __restrict__ bias, float* __restrict__ C,
               int M, int N, int K) {
    extern __shared__ uint32_t sm[];

    int tid = threadIdx.x;
    int wid = tid >> 5, lane = tid & 31;
    int g = lane >> 2, tc = lane & 3;
    int wm0 = (wid & 3) * 32, wn0 = (wid >> 2) * 64;
    int m0 = blockIdx.y * 128, n0 = blockIdx.x * 128;

    int arow = tid >> 3, ac4 = (tid & 7) * 4;   // A loader: 32 rows x 8 thr
    int brow = tid >> 5, bc4 = (tid & 31) * 4;  // B loader: 8 rows x 32 thr

    const float* Abase = A + (size_t)(m0 + arow) * K + ac4;
    const float* Bbase = B + (size_t)brow * N + n0 + bc4;

    float acc[2][8][4];
#pragma unroll
    for (int mf = 0; mf < 2; mf++)
#pragma unroll
        for (int nf = 0; nf < 8; nf++)
#pragma unroll
            for (int e = 0; e < 4; e++) acc[mf][nf][e] = 0.f;

    float4 av[4], bv[4];
    // prologue: load k0=0, store stage 0
#pragma unroll
    for (int it = 0; it < 4; it++)
        av[it] = *(const float4*)(Abase + (size_t)(32*it) * K);
#pragma unroll
    for (int it = 0; it < 4; it++)
        bv[it] = *(const float4*)(Bbase + (size_t)(8*it) * N);
    {
        uint32_t* As = sm;
        uint32_t* Bs = sm + AS_W;
#pragma unroll
        for (int it = 0; it < 4; it++) {
            uint32_t* p = As + (arow + 32*it) * 36 + ac4;
            p[0] = f2tf32(av[it].x); p[1] = f2tf32(av[it].y);
            p[2] = f2tf32(av[it].z); p[3] = f2tf32(av[it].w);
        }
#pragma unroll
        for (int it = 0; it < 4; it++) {
            uint32_t* p = Bs + (brow + 8*it) * 136 + bc4;
            p[0] = f2tf32(bv[it].x); p[1] = f2tf32(bv[it].y);
            p[2] = f2tf32(bv[it].z); p[3] = f2tf32(bv[it].w);
        }
    }
    __syncthreads();

    int niter = K >> 5;
    for (int it0 = 0; it0 < niter; it0++) {
        // prefetch next K-slab into registers (hidden under MMA below)
        if (it0 + 1 < niter) {
            int k0 = (it0 + 1) << 5;
#pragma unroll
            for (int it = 0; it < 4; it++)
                av[it] = *(const float4*)(Abase + (size_t)(32*it) * K + k0);
#pragma unroll
            for (int it = 0; it < 4; it++)
                bv[it] = *(const float4*)(Bbase + (size_t)(k0 + 8*it) * N);
        }

        const uint32_t* As = sm + (it0 & 1) * BUF_W;
        const uint32_t* Bs = As + AS_W;
#pragma unroll
        for (int ks = 0; ks < 4; ks++) {
            int kk = ks * 8;
            uint32_t a[2][4];
#pragma unroll
            for (int mf = 0; mf < 2; mf++) {
                const uint32_t* r0 = As + (wm0 + mf*16 + g) * 36 + kk + tc;
                const uint32_t* r1 = r0 + 8 * 36;
                a[mf][0] = r0[0];
                a[mf][1] = r1[0];
                a[mf][2] = r0[4];
                a[mf][3] = r1[4];
            }
#pragma unroll
            for (int nf = 0; nf < 8; nf++) {
                int cn = wn0 + nf*8 + g;
                uint32_t b0 = Bs[(kk + tc) * 136 + cn];
                uint32_t b1 = Bs[(kk + tc + 4) * 136 + cn];
                mma8(acc[0][nf], a[0], b0, b1);
                mma8(acc[1][nf], a[1], b0, b1);
            }
        }

        if (it0 + 1 < niter) {
            uint32_t* nAs = sm + ((it0 + 1) & 1) * BUF_W;
            uint32_t* nBs = nAs + AS_W;
#pragma unroll
            for (int it = 0; it < 4; it++) {
                uint32_t* p = nAs + (arow + 32*it) * 36 + ac4;
                p[0] = f2tf32(av[it].x); p[1] = f2tf32(av[it].y);
                p[2] = f2tf32(av[it].z); p[3] = f2tf32(av[it].w);
            }
#pragma unroll
            for (int it = 0; it < 4; it++) {
                uint32_t* p = nBs + (brow + 8*it) * 136 + bc4;
                p[0] = f2tf32(bv[it].x); p[1] = f2tf32(bv[it].y);
                p[2] = f2tf32(bv[it].z); p[3] = f2tf32(bv[it].w);
            }
            __syncthreads();
        }
    }

    // ---- epilogue ----
#pragma unroll
    for (int mf = 0; mf < 2; mf++) {
#pragma unroll
        for (int half = 0; half < 2; half++) {
            int row = m0 + wm0 + mf*16 + g + half*8;
#pragma unroll
            for (int nf = 0; nf < 8; nf++) {
                int col = n0 + wn0 + nf*8 + tc*2;
                float v0 = acc[mf][nf][half*2 + 0] + bias[col];
                float v1 = acc[mf][nf][half*2 + 1] + bias[col + 1];
                if (MODE == 1) { v0 = fmaxf(v0, 0.f); v1 = fmaxf(v1, 0.f); }
                if (MODE == 2) {
                    // col already planar: wh*512 + h*64 + dh
                    int b = row >> 9, t = row & 511;
                    int wh = col >> 9, rem = col & 511;
                    int h = rem >> 6, dh = rem & 63;
                    float* dst = C + (size_t)wh * PLANE
                               + (((size_t)(b*HH + h)) * TT + t) * DH + dh;
                    *(float2*)dst = make_float2(v0, v1);
                } else {
                    *(float2*)(C + (size_t)row * N + col) = make_float2(v0, v1);
                }
            }
        }
    }
}

// ---------------------------------------------------------------------------
// Attention: planar Q/K/V [B,H,T,Dh], 1 thread = 1 query, online softmax.
// grid: (B*H, 4), block: 128
// ---------------------------------------------------------------------------
__global__ __launch_bounds__(128)
void attn_kernel(const float* __restrict__ qkv, const int* __restrict__ track_ids,
                 float* __restrict__ y) {
    __shared__ float Ks[16][64];
    __shared__ float Vs[16][64];
    __shared__ float padf[16];

    int bh = blockIdx.x;
    int b = bh >> 3, h = bh & 7;
    int q = blockIdx.y * 128 + threadIdx.x;
    int tid = threadIdx.x;

    const float* qpl = qkv;
    const float* kpl = qkv + PLANE;
    const float* vpl = qkv + 2 * PLANE;
    size_t hb = ((size_t)(b*HH + h)) * TT * DH;

    float qreg[64];
#pragma unroll
    for (int d4 = 0; d4 < 16; d4++) {
        float4 v = *(const float4*)(qpl + hb + (size_t)q * DH + d4*4);
        qreg[d4*4+0] = v.x; qreg[d4*4+1] = v.y;
        qreg[d4*4+2] = v.z; qreg[d4*4+3] = v.w;
    }

    float acc[64];
#pragma unroll
    for (int d = 0; d < 64; d++) acc[d] = 0.f;
    float m = -1e30f, ssum = 0.f;

    int nt = (blockIdx.y + 1) * 128;
    int qw = q | 31;

    for (int t0 = 0; t0 < TT; t0 += 16) {
        if (t0 >= nt) {
            if (__syncthreads_and(m > -5000.f)) break;
        }
        __syncthreads();
#pragma unroll
        for (int it = 0; it < 2; it++) {
            int e = tid + it * 128;
            int j = e >> 4, c4 = e & 15;
            ((float4*)&Ks[j][0])[c4] = *(const float4*)(kpl + hb + (size_t)(t0 + j)*DH + c4*4);
            ((float4*)&Vs[j][0])[c4] = *(const float4*)(vpl + hb + (size_t)(t0 + j)*DH + c4*4);
        }
        if (tid < 16)
            padf[tid] = (track_ids[b * TT + t0 + tid] != 0) ? 1.f : 0.f;
        __syncthreads();

        if (t0 <= qw || m <= -5000.f) {
            float s[16];
            float tmax = -1e30f;
#pragma unroll
            for (int j = 0; j < 16; j++) {
                float dot = 0.f;
                const float4* K4 = (const float4*)Ks[j];
#pragma unroll
                for (int d4 = 0; d4 < 16; d4++) {
                    float4 kk = K4[d4];
                    dot = fmaf(qreg[d4*4+0], kk.x, dot);
                    dot = fmaf(qreg[d4*4+1], kk.y, dot);
                    dot = fmaf(qreg[d4*4+2], kk.z, dot);
                    dot = fmaf(qreg[d4*4+3], kk.w, dot);
                }
                bool ok = ((t0 + j) <= q) && (padf[j] != 0.f);
                float sc = dot * 0.125f + (ok ? 0.f : -10000.f);
                s[j] = sc;
                tmax = fmaxf(tmax, sc);
            }
            float mn = fmaxf(m, tmax);
            float corr = __expf(m - mn);
            ssum *= corr;
#pragma unroll
            for (int d = 0; d < 64; d++) acc[d] *= corr;
#pragma unroll
            for (int j = 0; j < 16; j++) {
                float p = __expf(s[j] - mn);
                ssum += p;
                const float4* V4 = (const float4*)Vs[j];
#pragma unroll
                for (int d4 = 0; d4 < 16; d4++) {
                    float4 vv = V4[d4];
                    acc[d4*4+0] = fmaf(p, vv.x, acc[d4*4+0]);
                    acc[d4*4+1] = fmaf(p, vv.y, acc[d4*4+1]);
                    acc[d4*4+2] = fmaf(p, vv.z, acc[d4*4+2]);
                    acc[d4*4+3] = fmaf(p, vv.w, acc[d4*4+3]);
                }
            }
            m = mn;
        }
    }

    float inv = 1.f / ssum;
    float* yp = y + (size_t)(b * TT + q) * DD + h * DH;
#pragma unroll
    for (int d4 = 0; d4 < 16; d4++) {
        float4 o;
        o.x = acc[d4*4+0] * inv;
        o.y = acc[d4*4+1] * inv;
        o.z = acc[d4*4+2] * inv;
        o.w = acc[d4*4+3] * inv;
        *(float4*)(yp + d4*4) = o;
    }
}

// ---------------------------------------------------------------------------
// Fused residual + LayerNorm: out = LN(x + y) * g + b. One warp per token.
// ---------------------------------------------------------------------------
__global__ void add_ln_kernel(const float* __restrict__ x, const float* __restrict__ y,
                              const float* __restrict__ g, const float* __restrict__ b,
                              float* __restrict__ out) {
    int token = blockIdx.x * 8 + (threadIdx.x >> 5);
    int lane = threadIdx.x & 31;
    const float4* xr = (const float4*)(x + (size_t)token * DD);
    const float4* yr = (const float4*)(y + (size_t)token * DD);

    float4 v[4];
    float s = 0.f;
#pragma unroll
    for (int c = 0; c < 4; c++) {
        float4 a = xr[lane + 32*c];
        float4 w = yr[lane + 32*c];
        v[c].x = a.x + w.x; v[c].y = a.y + w.y;
        v[c].z = a.z + w.z; v[c].w = a.w + w.w;
        s += v[c].x + v[c].y + v[c].z + v[c].w;
    }
#pragma unroll
    for (int off = 16; off; off >>= 1) s += __shfl_xor_sync(0xffffffffu, s, off);
    float mu = s * (1.f / 512.f);

    float sq = 0.f;
#pragma unroll
    for (int c = 0; c < 4; c++) {
        float dx = v[c].x - mu, dy = v[c].y - mu, dz = v[c].z - mu, dw = v[c].w - mu;
        sq += dx*dx + dy*dy + dz*dz + dw*dw;
    }
#pragma unroll
    for (int off = 16; off; off >>= 1) sq += __shfl_xor_sync(0xffffffffu, sq, off);
    float r = rsqrtf(sq * (1.f / 512.f) + 1e-5f);

    const float4* g4 = (const float4*)g;
    const float4* b4 = (const float4*)b;
    float4* orow = (float4*)(out + (size_t)token * DD);
#pragma unroll
    for (int c = 0; c < 4; c++) {
        int idx = lane + 32*c;
        float4 gg = g4[idx], bb = b4[idx];
        float4 o;
        o.x = (v[c].x - mu) * r * gg.x + bb.x;
        o.y = (v[c].y - mu) * r * gg.y + bb.y;
        o.z = (v[c].z - mu) * r * gg.z + bb.z;
        o.w = (v[c].w - mu) * r * gg.w + bb.w;
        orow[idx] = o;
    }
}

// ---------------------------------------------------------------------------
extern "C" void kernel_launch(void* const* d_in, const int* in_sizes, int n_in,
                              void* d_out, int out_size) {
    const int*   track_ids  = (const int*)  d_in[0];
    const int*   artist_ids = (const int*)  d_in[1];
    const float* track_emb  = (const float*)d_in[2];
    const float* artist_emb = (const float*)d_in[3];
    const float* pos_emb    = (const float*)d_in[4];
    const float* Wqkv       = (const float*)d_in[5];
    const float* bqkv       = (const float*)d_in[6];
    const float* Wff        = (const float*)d_in[7];
    const float* bff        = (const float*)d_in[8];
    const float* Wout       = (const float*)d_in[9];
    const float* bout       = (const float*)d_in[10];
    const float* g1         = (const float*)d_in[11];
    const float* b1         = (const float*)d_in[12];
    const float* g2         = (const float*)d_in[13];
    const float* b2         = (const float*)d_in[14];
    float* out = (float*)d_out;

    float *x, *qkv, *y, *h, *wp, *bp;
    cudaGetSymbolAddress((void**)&x,   g_x);
    cudaGetSymbolAddress((void**)&qkv, g_qkv);
    cudaGetSymbolAddress((void**)&y,   g_y);
    cudaGetSymbolAddress((void**)&h,   g_h);
    cudaGetSymbolAddress((void**)&wp,  g_wp);
    cudaGetSymbolAddress((void**)&bp,  g_bp);

    cudaFuncSetAttribute(gemm_tf32<0>, cudaFuncAttributeMaxDynamicSharedMemorySize, GEMM_SMEM);
    cudaFuncSetAttribute(gemm_tf32<1>, cudaFuncAttributeMaxDynamicSharedMemorySize, GEMM_SMEM);
    cudaFuncSetAttribute(gemm_tf32<2>, cudaFuncAttributeMaxDynamicSharedMemorySize, GEMM_SMEM);

    embed_kernel<<<NTOK, 128>>>(track_ids, artist_ids, track_emb, artist_emb, pos_emb);

    for (int i = 0; i < LL; i++) {
        // permute this layer's QKV weight columns into planar order
        permute_wqkv<<<dim3(6, 512), 256>>>(Wqkv + (size_t)i * DD * (3*DD),
                                            bqkv + (size_t)i * (3*DD));
        // QKV projection (planar output): [16384,512] x [512,1536]
        gemm_tf32<2><<<dim3((3*DD)/128, NTOK/128), 256, GEMM_SMEM>>>(
            x, wp, bp, qkv, NTOK, 3*DD, DD);
        // Attention
        attn_kernel<<<dim3(BB*HH, 4), 128>>>(qkv, track_ids, y);
        // x = LN(x + attn)
        add_ln_kernel<<<NTOK/8, 256>>>(x, y, g1 + (size_t)i*DD, b1 + (size_t)i*DD, x);
        // FF1 (+ReLU): [16384,512] x [512,2048]
        gemm_tf32<1><<<dim3(DFF/128, NTOK/128), 256, GEMM_SMEM>>>(
            x, Wff + (size_t)i * DD * DFF, bff + (size_t)i * DFF, h,
            NTOK, DFF, DD);
        // FF2: [16384,2048] x [2048,512]
        gemm_tf32<0><<<dim3(DD/128, NTOK/128), 256, GEMM_SMEM>>>(
            h, Wout + (size_t)i * DFF * DD, bout + (size_t)i * DD, y,
            NTOK, DD, DFF);
        // x = LN(x + ff)  (last layer writes straight to output)
        add_ln_kernel<<<NTOK/8, 256>>>(x, y, g2 + (size_t)i*DD, b2 + (size_t)i*DD,
                                       (i == LL-1) ? out : x);
    }
}

// round 4
// speedup vs baseline: 3.3667x; 1.3879x over previous
#include <cuda_runtime.h>
#include <cstdint>

// ---------------------------------------------------------------------------
// Decoder: 6-layer transformer, B=32, T=512, D=512 (H=8, Dh=64), DFF=2048
// Round 3: tensor-core (tf32 mma) flash attention; GEMMs as round 2
// ---------------------------------------------------------------------------

#define BB   32
#define TT   512
#define HH   8
#define DH   64
#define DD   512
#define DFF  2048
#define LL   6
#define NTOK (BB*TT)          // 16384
#define PLANE ((size_t)NTOK * DD)

__device__ float g_x  [(size_t)NTOK * DD];
__device__ float g_qkv[(size_t)NTOK * 3*DD];
__device__ float g_y  [(size_t)NTOK * DD];
__device__ float g_h  [(size_t)NTOK * DFF];
__device__ float g_wp [(size_t)DD * 3*DD];
__device__ float g_bp [3*DD];

__device__ __forceinline__ uint32_t f2tf32(float f) {
    uint32_t u;
    asm("cvt.rna.tf32.f32 %0, %1;" : "=r"(u) : "f"(f));
    return u;
}

__device__ __forceinline__ void mma8(float* c, const uint32_t* a, uint32_t b0, uint32_t b1) {
    asm volatile(
        "mma.sync.aligned.m16n8k8.row.col.f32.tf32.tf32.f32 "
        "{%0,%1,%2,%3}, {%4,%5,%6,%7}, {%8,%9}, {%0,%1,%2,%3};"
        : "+f"(c[0]), "+f"(c[1]), "+f"(c[2]), "+f"(c[3])
        : "r"(a[0]), "r"(a[1]), "r"(a[2]), "r"(a[3]), "r"(b0), "r"(b1));
}

// ---------------------------------------------------------------------------
__global__ void embed_kernel(const int* __restrict__ tids, const int* __restrict__ aids,
                             const float* __restrict__ te, const float* __restrict__ ae,
                             const float* __restrict__ pe) {
    int token = blockIdx.x;
    int t = token & (TT - 1);
    int ti = tids[token], ai = aids[token];
    int d = threadIdx.x * 4;
    float4 t4 = *(const float4*)(te + (size_t)ti * DD + d);
    float4 a4 = *(const float4*)(ae + (size_t)ai * DD + d);
    float4 p4 = *(const float4*)(pe + (size_t)t  * DD + d);
    float4 o;
    o.x = 0.5f*(t4.x + a4.x) + p4.x;
    o.y = 0.5f*(t4.y + a4.y) + p4.y;
    o.z = 0.5f*(t4.z + a4.z) + p4.z;
    o.w = 0.5f*(t4.w + a4.w) + p4.w;
    *(float4*)(g_x + (size_t)token * DD + d) = o;
}

// ---------------------------------------------------------------------------
__global__ void permute_wqkv(const float* __restrict__ W, const float* __restrict__ bias) {
    int n = blockIdx.x * 256 + threadIdx.x;
    int k = blockIdx.y;
    int wh = n >> 9, rem = n & 511;
    int h = rem >> 6, dh = rem & 63;
    int o = h * 192 + dh * 3 + wh;
    g_wp[(size_t)k * (3*DD) + n] = W[(size_t)k * (3*DD) + o];
    if (k == 0) g_bp[n] = bias[o];
}

// ---------------------------------------------------------------------------
// tf32 GEMM (round-2 pipelined version, unchanged)
// ---------------------------------------------------------------------------
#define AS_W 4608
#define BS_W 4352
#define BUF_W (AS_W + BS_W)
#define GEMM_SMEM (2 * BUF_W * 4)

template<int MODE>
__global__ __launch_bounds__(256, 2)
void gemm_tf32(const float* __restrict__ A, const float* __restrict__ B,
               const float* __restrict__ bias, float* __restrict__ C,
               int M, int N, int K) {
    extern __shared__ uint32_t sm[];

    int tid = threadIdx.x;
    int wid = tid >> 5, lane = tid & 31;
    int g = lane >> 2, tc = lane & 3;
    int wm0 = (wid & 3) * 32, wn0 = (wid >> 2) * 64;
    int m0 = blockIdx.y * 128, n0 = blockIdx.x * 128;

    int arow = tid >> 3, ac4 = (tid & 7) * 4;
    int brow = tid >> 5, bc4 = (tid & 31) * 4;

    const float* Abase = A + (size_t)(m0 + arow) * K + ac4;
    const float* Bbase = B + (size_t)brow * N + n0 + bc4;

    float acc[2][8][4];
#pragma unroll
    for (int mf = 0; mf < 2; mf++)
#pragma unroll
        for (int nf = 0; nf < 8; nf++)
#pragma unroll
            for (int e = 0; e < 4; e++) acc[mf][nf][e] = 0.f;

    float4 av[4], bv[4];
#pragma unroll
    for (int it = 0; it < 4; it++)
        av[it] = *(const float4*)(Abase + (size_t)(32*it) * K);
#pragma unroll
    for (int it = 0; it < 4; it++)
        bv[it] = *(const float4*)(Bbase + (size_t)(8*it) * N);
    {
        uint32_t* As = sm;
        uint32_t* Bs = sm + AS_W;
#pragma unroll
        for (int it = 0; it < 4; it++) {
            uint32_t* p = As + (arow + 32*it) * 36 + ac4;
            p[0] = f2tf32(av[it].x); p[1] = f2tf32(av[it].y);
            p[2] = f2tf32(av[it].z); p[3] = f2tf32(av[it].w);
        }
#pragma unroll
        for (int it = 0; it < 4; it++) {
            uint32_t* p = Bs + (brow + 8*it) * 136 + bc4;
            p[0] = f2tf32(bv[it].x); p[1] = f2tf32(bv[it].y);
            p[2] = f2tf32(bv[it].z); p[3] = f2tf32(bv[it].w);
        }
    }
    __syncthreads();

    int niter = K >> 5;
    for (int it0 = 0; it0 < niter; it0++) {
        if (it0 + 1 < niter) {
            int k0 = (it0 + 1) << 5;
#pragma unroll
            for (int it = 0; it < 4; it++)
                av[it] = *(const float4*)(Abase + (size_t)(32*it) * K + k0);
#pragma unroll
            for (int it = 0; it < 4; it++)
                bv[it] = *(const float4*)(Bbase + (size_t)(k0 + 8*it) * N);
        }

        const uint32_t* As = sm + (it0 & 1) * BUF_W;
        const uint32_t* Bs = As + AS_W;
#pragma unroll
        for (int ks = 0; ks < 4; ks++) {
            int kk = ks * 8;
            uint32_t a[2][4];
#pragma unroll
            for (int mf = 0; mf < 2; mf++) {
                const uint32_t* r0 = As + (wm0 + mf*16 + g) * 36 + kk + tc;
                const uint32_t* r1 = r0 + 8 * 36;
                a[mf][0] = r0[0];
                a[mf][1] = r1[0];
                a[mf][2] = r0[4];
                a[mf][3] = r1[4];
            }
#pragma unroll
            for (int nf = 0; nf < 8; nf++) {
                int cn = wn0 + nf*8 + g;
                uint32_t b0 = Bs[(kk + tc) * 136 + cn];
                uint32_t b1 = Bs[(kk + tc + 4) * 136 + cn];
                mma8(acc[0][nf], a[0], b0, b1);
                mma8(acc[1][nf], a[1], b0, b1);
            }
        }

        if (it0 + 1 < niter) {
            uint32_t* nAs = sm + ((it0 + 1) & 1) * BUF_W;
            uint32_t* nBs = nAs + AS_W;
#pragma unroll
            for (int it = 0; it < 4; it++) {
                uint32_t* p = nAs + (arow + 32*it) * 36 + ac4;
                p[0] = f2tf32(av[it].x); p[1] = f2tf32(av[it].y);
                p[2] = f2tf32(av[it].z); p[3] = f2tf32(av[it].w);
            }
#pragma unroll
            for (int it = 0; it < 4; it++) {
                uint32_t* p = nBs + (brow + 8*it) * 136 + bc4;
                p[0] = f2tf32(bv[it].x); p[1] = f2tf32(bv[it].y);
                p[2] = f2tf32(bv[it].z); p[3] = f2tf32(bv[it].w);
            }
            __syncthreads();
        }
    }

#pragma unroll
    for (int mf = 0; mf < 2; mf++) {
#pragma unroll
        for (int half = 0; half < 2; half++) {
            int row = m0 + wm0 + mf*16 + g + half*8;
#pragma unroll
            for (int nf = 0; nf < 8; nf++) {
                int col = n0 + wn0 + nf*8 + tc*2;
                float v0 = acc[mf][nf][half*2 + 0] + bias[col];
                float v1 = acc[mf][nf][half*2 + 1] + bias[col + 1];
                if (MODE == 1) { v0 = fmaxf(v0, 0.f); v1 = fmaxf(v1, 0.f); }
                if (MODE == 2) {
                    int b = row >> 9, t = row & 511;
                    int wh = col >> 9, rem = col & 511;
                    int h = rem >> 6, dh = rem & 63;
                    float* dst = C + (size_t)wh * PLANE
                               + (((size_t)(b*HH + h)) * TT + t) * DH + dh;
                    *(float2*)dst = make_float2(v0, v1);
                } else {
                    *(float2*)(C + (size_t)row * N + col) = make_float2(v0, v1);
                }
            }
        }
    }
}

// ---------------------------------------------------------------------------
// Tensor-core flash attention.
// Block: 128 queries x one (b,h). 8 warps x 16 queries. Key tiles of 64.
// Q pre-scaled by 0.125, tf32 in smem. QK^T and PV via m16n8k8 tf32 mma.
// Online softmax in mma C-layout; P relayout C->A via lane shuffles.
// grid (B*H, 4), block 256.
// ---------------------------------------------------------------------------
#define QS_W (128*68)
#define KS_W (64*68)
#define VS_W (64*68)
#define ATT_SMEM ((QS_W + KS_W + VS_W + 64) * 4)

__global__ __launch_bounds__(256, 2)
void attn_kernel(const float* __restrict__ qkv, const int* __restrict__ track_ids,
                 float* __restrict__ y) {
    extern __shared__ uint32_t sma[];
    uint32_t* Qs = sma;                 // [128][68] tf32
    uint32_t* Ks = Qs + QS_W;           // [64][68]  tf32
    uint32_t* Vs = Ks + KS_W;           // [64][68]  tf32
    float*    padsm = (float*)(Vs + VS_W);  // [64]

    int tid = threadIdx.x;
    int wid = tid >> 5, lane = tid & 31;
    int g = lane >> 2, tc = lane & 3;
    int bh = blockIdx.x;
    int b = bh >> 3, h = bh & 7;
    int q0 = blockIdx.y * 128;
    int wq0 = wid * 16;

    const float* qpl = qkv;
    const float* kpl = qkv + PLANE;
    const float* vpl = qkv + 2 * PLANE;
    size_t hb = ((size_t)(b*HH + h)) * TT * DH;

    // load Q tile (128x64), pre-scaled by 0.125, as tf32
    {
        int r = tid >> 4, c4 = (tid & 15) * 4;
#pragma unroll
        for (int it = 0; it < 8; it++) {
            int row = r + it * 16;
            float4 v = *(const float4*)(qpl + hb + (size_t)(q0 + row) * DH + c4);
            uint32_t* p = Qs + row * 68 + c4;
            p[0] = f2tf32(v.x * 0.125f); p[1] = f2tf32(v.y * 0.125f);
            p[2] = f2tf32(v.z * 0.125f); p[3] = f2tf32(v.w * 0.125f);
        }
    }

    float o_acc[8][4];
#pragma unroll
    for (int vf = 0; vf < 8; vf++)
#pragma unroll
        for (int e = 0; e < 4; e++) o_acc[vf][e] = 0.f;
    float m0r = -1e30f, m1r = -1e30f, l0r = 0.f, l1r = 0.f;

    int q_r0 = q0 + wq0 + g;
    int q_r1 = q_r0 + 8;
    int causal_tiles = (blockIdx.y + 1) * 2;   // 64-key tiles within causal bound

    for (int kt = 0; kt < TT/64; kt++) {
        if (kt >= causal_tiles) {
            if (__syncthreads_and(m0r > -5000.f && m1r > -5000.f)) break;
        }
        __syncthreads();
        // load K/V tile (64x64) as tf32
        {
            int r = tid >> 4, c4 = (tid & 15) * 4;
#pragma unroll
            for (int it = 0; it < 4; it++) {
                int row = r + it * 16;
                float4 kv4 = *(const float4*)(kpl + hb + (size_t)(kt*64 + row) * DH + c4);
                float4 vv4 = *(const float4*)(vpl + hb + (size_t)(kt*64 + row) * DH + c4);
                uint32_t* pk = Ks + row * 68 + c4;
                uint32_t* pv = Vs + row * 68 + c4;
                pk[0] = f2tf32(kv4.x); pk[1] = f2tf32(kv4.y);
                pk[2] = f2tf32(kv4.z); pk[3] = f2tf32(kv4.w);
                pv[0] = f2tf32(vv4.x); pv[1] = f2tf32(vv4.y);
                pv[2] = f2tf32(vv4.z); pv[3] = f2tf32(vv4.w);
            }
            if (tid < 64)
                padsm[tid] = (track_ids[b * TT + kt*64 + tid] != 0) ? 1.f : 0.f;
        }
        __syncthreads();

        // ---- S = Qs @ Ks^T  (16 q x 64 keys per warp) ----
        float sacc[8][4];
#pragma unroll
        for (int nf = 0; nf < 8; nf++)
#pragma unroll
            for (int e = 0; e < 4; e++) sacc[nf][e] = 0.f;
#pragma unroll
        for (int ks = 0; ks < 8; ks++) {
            int kk = ks * 8;
            uint32_t a[4];
            const uint32_t* r0 = Qs + (wq0 + g) * 68 + kk + tc;
            const uint32_t* r1 = r0 + 8 * 68;
            a[0] = r0[0]; a[1] = r1[0]; a[2] = r0[4]; a[3] = r1[4];
#pragma unroll
            for (int nf = 0; nf < 8; nf++) {
                const uint32_t* kr = Ks + (nf*8 + g) * 68 + kk + tc;
                mma8(sacc[nf], a, kr[0], kr[4]);
            }
        }

        // ---- mask + online softmax ----
        float tmax0 = -1e30f, tmax1 = -1e30f;
#pragma unroll
        for (int nf = 0; nf < 8; nf++) {
            int kcol = kt*64 + nf*8 + tc*2;
#pragma unroll
            for (int e = 0; e < 2; e++) {
                int key = kcol + e;
                float pad = padsm[key - kt*64];
                float s0 = sacc[nf][e]   + ((key <= q_r0 && pad != 0.f) ? 0.f : -10000.f);
                float s1 = sacc[nf][e+2] + ((key <= q_r1 && pad != 0.f) ? 0.f : -10000.f);
                sacc[nf][e] = s0; sacc[nf][e+2] = s1;
                tmax0 = fmaxf(tmax0, s0);
                tmax1 = fmaxf(tmax1, s1);
            }
        }
        tmax0 = fmaxf(tmax0, __shfl_xor_sync(0xffffffffu, tmax0, 1));
        tmax0 = fmaxf(tmax0, __shfl_xor_sync(0xffffffffu, tmax0, 2));
        tmax1 = fmaxf(tmax1, __shfl_xor_sync(0xffffffffu, tmax1, 1));
        tmax1 = fmaxf(tmax1, __shfl_xor_sync(0xffffffffu, tmax1, 2));

        float mn0 = fmaxf(m0r, tmax0), mn1 = fmaxf(m1r, tmax1);
        float c0 = __expf(m0r - mn0),  c1 = __expf(m1r - mn1);
        m0r = mn0; m1r = mn1;

        float ls0 = 0.f, ls1 = 0.f;
#pragma unroll
        for (int nf = 0; nf < 8; nf++) {
#pragma unroll
            for (int e = 0; e < 2; e++) {
                float p0 = __expf(sacc[nf][e]   - mn0);
                float p1 = __expf(sacc[nf][e+2] - mn1);
                ls0 += p0; ls1 += p1;
                sacc[nf][e]   = __uint_as_float(f2tf32(p0));
                sacc[nf][e+2] = __uint_as_float(f2tf32(p1));
            }
        }
        ls0 += __shfl_xor_sync(0xffffffffu, ls0, 1);
        ls0 += __shfl_xor_sync(0xffffffffu, ls0, 2);
        ls1 += __shfl_xor_sync(0xffffffffu, ls1, 1);
        ls1 += __shfl_xor_sync(0xffffffffu, ls1, 2);
        l0r = l0r * c0 + ls0;
        l1r = l1r * c1 + ls1;

#pragma unroll
        for (int vf = 0; vf < 8; vf++) {
            o_acc[vf][0] *= c0; o_acc[vf][1] *= c0;
            o_acc[vf][2] *= c1; o_acc[vf][3] *= c1;
        }

        // ---- O += P @ V : relayout P (C-layout -> A-layout) via shuffles ----
        int sl1 = (lane & 28) | (tc >> 1);
        int sl2 = sl1 + 2;
        bool odd = (tc & 1);
#pragma unroll
        for (int ks = 0; ks < 8; ks++) {
            float p00 = __shfl_sync(0xffffffffu, sacc[ks][0], sl1);
            float p01 = __shfl_sync(0xffffffffu, sacc[ks][1], sl1);
            float p02 = __shfl_sync(0xffffffffu, sacc[ks][2], sl1);
            float p03 = __shfl_sync(0xffffffffu, sacc[ks][3], sl1);
            float p10 = __shfl_sync(0xffffffffu, sacc[ks][0], sl2);
            float p11 = __shfl_sync(0xffffffffu, sacc[ks][1], sl2);
            float p12 = __shfl_sync(0xffffffffu, sacc[ks][2], sl2);
            float p13 = __shfl_sync(0xffffffffu, sacc[ks][3], sl2);
            uint32_t a[4];
            a[0] = __float_as_uint(odd ? p01 : p00);
            a[1] = __float_as_uint(odd ? p03 : p02);
            a[2] = __float_as_uint(odd ? p11 : p10);
            a[3] = __float_as_uint(odd ? p13 : p12);
            const uint32_t* v0 = Vs + (ks*8 + tc) * 68 + g;
            const uint32_t* v1 = v0 + 4 * 68;
#pragma unroll
            for (int vf = 0; vf < 8; vf++)
                mma8(o_acc[vf], a, v0[vf*8], v1[vf*8]);
        }
    }

    // ---- write out: y[b, t, h*64 + dh] ----
    float inv0 = 1.f / l0r, inv1 = 1.f / l1r;
    float* y0 = y + (size_t)(b * TT + q_r0) * DD + h * DH;
    float* y1 = y + (size_t)(b * TT + q_r1) * DD + h * DH;
#pragma unroll
    for (int vf = 0; vf < 8; vf++) {
        int dh = vf*8 + tc*2;
        *(float2*)(y0 + dh) = make_float2(o_acc[vf][0] * inv0, o_acc[vf][1] * inv0);
        *(float2*)(y1 + dh) = make_float2(o_acc[vf][2] * inv1, o_acc[vf][3] * inv1);
    }
}

// ---------------------------------------------------------------------------
__global__ void add_ln_kernel(const float* __restrict__ x, const float* __restrict__ y,
                              const float* __restrict__ g, const float* __restrict__ b,
                              float* __restrict__ out) {
    int token = blockIdx.x * 8 + (threadIdx.x >> 5);
    int lane = threadIdx.x & 31;
    const float4* xr = (const float4*)(x + (size_t)token * DD);
    const float4* yr = (const float4*)(y + (size_t)token * DD);

    float4 v[4];
    float s = 0.f;
#pragma unroll
    for (int c = 0; c < 4; c++) {
        float4 a = xr[lane + 32*c];
        float4 w = yr[lane + 32*c];
        v[c].x = a.x + w.x; v[c].y = a.y + w.y;
        v[c].z = a.z + w.z; v[c].w = a.w + w.w;
        s += v[c].x + v[c].y + v[c].z + v[c].w;
    }
#pragma unroll
    for (int off = 16; off; off >>= 1) s += __shfl_xor_sync(0xffffffffu, s, off);
    float mu = s * (1.f / 512.f);

    float sq = 0.f;
#pragma unroll
    for (int c = 0; c < 4; c++) {
        float dx = v[c].x - mu, dy = v[c].y - mu, dz = v[c].z - mu, dw = v[c].w - mu;
        sq += dx*dx + dy*dy + dz*dz + dw*dw;
    }
#pragma unroll
    for (int off = 16; off; off >>= 1) sq += __shfl_xor_sync(0xffffffffu, sq, off);
    float r = rsqrtf(sq * (1.f / 512.f) + 1e-5f);

    const float4* g4 = (const float4*)g;
    const float4* b4 = (const float4*)b;
    float4* orow = (float4*)(out + (size_t)token * DD);
#pragma unroll
    for (int c = 0; c < 4; c++) {
        int idx = lane + 32*c;
        float4 gg = g4[idx], bb = b4[idx];
        float4 o;
        o.x = (v[c].x - mu) * r * gg.x + bb.x;
        o.y = (v[c].y - mu) * r * gg.y + bb.y;
        o.z = (v[c].z - mu) * r * gg.z + bb.z;
        o.w = (v[c].w - mu) * r * gg.w + bb.w;
        orow[idx] = o;
    }
}

// ---------------------------------------------------------------------------
extern "C" void kernel_launch(void* const* d_in, const int* in_sizes, int n_in,
                              void* d_out, int out_size) {
    const int*   track_ids  = (const int*)  d_in[0];
    const float* track_emb  = (const float*)d_in[2];
    const float* artist_emb = (const float*)d_in[3];
    const float* pos_emb    = (const float*)d_in[4];
    const float* Wqkv       = (const float*)d_in[5];
    const float* bqkv       = (const float*)d_in[6];
    const float* Wff        = (const float*)d_in[7];
    const float* bff        = (const float*)d_in[8];
    const float* Wout       = (const float*)d_in[9];
    const float* bout       = (const float*)d_in[10];
    const float* g1         = (const float*)d_in[11];
    const float* b1         = (const float*)d_in[12];
    const float* g2         = (const float*)d_in[13];
    const float* b2         = (const float*)d_in[14];
    const int*   artist_ids = (const int*)  d_in[1];
    float* out = (float*)d_out;

    float *x, *qkv, *y, *h, *wp, *bp;
    cudaGetSymbolAddress((void**)&x,   g_x);
    cudaGetSymbolAddress((void**)&qkv, g_qkv);
    cudaGetSymbolAddress((void**)&y,   g_y);
    cudaGetSymbolAddress((void**)&h,   g_h);
    cudaGetSymbolAddress((void**)&wp,  g_wp);
    cudaGetSymbolAddress((void**)&bp,  g_bp);

    cudaFuncSetAttribute(gemm_tf32<0>, cudaFuncAttributeMaxDynamicSharedMemorySize, GEMM_SMEM);
    cudaFuncSetAttribute(gemm_tf32<1>, cudaFuncAttributeMaxDynamicSharedMemorySize, GEMM_SMEM);
    cudaFuncSetAttribute(gemm_tf32<2>, cudaFuncAttributeMaxDynamicSharedMemorySize, GEMM_SMEM);
    cudaFuncSetAttribute(attn_kernel,  cudaFuncAttributeMaxDynamicSharedMemorySize, ATT_SMEM);

    embed_kernel<<<NTOK, 128>>>(track_ids, artist_ids, track_emb, artist_emb, pos_emb);

    for (int i = 0; i < LL; i++) {
        permute_wqkv<<<dim3(6, 512), 256>>>(Wqkv + (size_t)i * DD * (3*DD),
                                            bqkv + (size_t)i * (3*DD));
        gemm_tf32<2><<<dim3((3*DD)/128, NTOK/128), 256, GEMM_SMEM>>>(
            x, wp, bp, qkv, NTOK, 3*DD, DD);
        attn_kernel<<<dim3(BB*HH, 4), 256, ATT_SMEM>>>(qkv, track_ids, y);
        add_ln_kernel<<<NTOK/8, 256>>>(x, y, g1 + (size_t)i*DD, b1 + (size_t)i*DD, x);
        gemm_tf32<1><<<dim3(DFF/128, NTOK/128), 256, GEMM_SMEM>>>(
            x, Wff + (size_t)i * DD * DFF, bff + (size_t)i * DFF, h,
            NTOK, DFF, DD);
        gemm_tf32<0><<<dim3(DD/128, NTOK/128), 256, GEMM_SMEM>>>(
            h, Wout + (size_t)i * DFF * DD, bout + (size_t)i * DD, y,
            NTOK, DD, DFF);
        add_ln_kernel<<<NTOK/8, 256>>>(x, y, g2 + (size_t)i*DD, b2 + (size_t)i*DD,
                                       (i == LL-1) ? out : x);
    }
}

// round 6
// speedup vs baseline: 4.6119x; 1.3698x over previous
#include <cuda_runtime.h>
#include <cuda_fp16.h>
#include <cstdint>

// ---------------------------------------------------------------------------
// Decoder: 6-layer transformer, B=32, T=512, D=512 (H=8, Dh=64), DFF=2048
// Round 5: fp16 m16n8k16 mma.sync GEMMs with cp.async pipeline
// (tcgen05 unavailable: harness ptxas targets sm_103 without 'a' features)
// ---------------------------------------------------------------------------

#define BB   32
#define TT   512
#define HH   8
#define DH   64
#define DD   512
#define DFF  2048
#define LL   6
#define NTOK (BB*TT)
#define PLANE ((size_t)NTOK * DD)

__device__ float  g_x   [(size_t)NTOK * DD];     // fp32 residual stream
__device__ __half g_x16 [(size_t)NTOK * DD];     // fp16 copy for GEMM A
__device__ float  g_qkv [(size_t)NTOK * 3*DD];   // fp32 planar [3][B,H,T,Dh]
__device__ float  g_y   [(size_t)NTOK * DD];     // fp32 sublayer output
__device__ __half g_h16 [(size_t)NTOK * DFF];    // fp16 FF hidden
__device__ float  g_wp  [(size_t)DD * 3*DD];     // permuted Wqkv fp32
__device__ float  g_bp  [3*DD];
__device__ __half g_wt16[(size_t)1 << 21];       // transposed fp16 weights [N,K]

__device__ __forceinline__ uint32_t f2tf32(float f) {
    uint32_t u;
    asm("cvt.rna.tf32.f32 %0, %1;" : "=r"(u) : "f"(f));
    return u;
}
__device__ __forceinline__ uint32_t smem_u32(const void* p) {
    uint32_t a;
    asm("{ .reg .u64 t; cvta.to.shared.u64 t, %1; cvt.u32.u64 %0, t; }" : "=r"(a) : "l"(p));
    return a;
}
__device__ __forceinline__ void mma8(float* c, const uint32_t* a, uint32_t b0, uint32_t b1) {
    asm volatile(
        "mma.sync.aligned.m16n8k8.row.col.f32.tf32.tf32.f32 "
        "{%0,%1,%2,%3}, {%4,%5,%6,%7}, {%8,%9}, {%0,%1,%2,%3};"
        : "+f"(c[0]), "+f"(c[1]), "+f"(c[2]), "+f"(c[3])
        : "r"(a[0]), "r"(a[1]), "r"(a[2]), "r"(a[3]), "r"(b0), "r"(b1));
}
__device__ __forceinline__ void mma16h(float* c, const uint32_t* a, uint32_t b0, uint32_t b1) {
    asm volatile(
        "mma.sync.aligned.m16n8k16.row.col.f32.f16.f16.f32 "
        "{%0,%1,%2,%3}, {%4,%5,%6,%7}, {%8,%9}, {%0,%1,%2,%3};"
        : "+f"(c[0]), "+f"(c[1]), "+f"(c[2]), "+f"(c[3])
        : "r"(a[0]), "r"(a[1]), "r"(a[2]), "r"(a[3]), "r"(b0), "r"(b1));
}
__device__ __forceinline__ void cp16(uint32_t dst, const void* src) {
    asm volatile("cp.async.cg.shared.global [%0], [%1], 16;" :: "r"(dst), "l"(src));
}
#define CP_COMMIT() asm volatile("cp.async.commit_group;" ::: "memory")
#define CP_WAIT(n)  asm volatile("cp.async.wait_group %0;" :: "n"(n) : "memory")

// ---------------------------------------------------------------------------
__global__ void embed_kernel(const int* __restrict__ tids, const int* __restrict__ aids,
                             const float* __restrict__ te, const float* __restrict__ ae,
                             const float* __restrict__ pe) {
    int token = blockIdx.x;
    int t = token & (TT - 1);
    int ti = tids[token], ai = aids[token];
    int d = threadIdx.x * 4;
    float4 t4 = *(const float4*)(te + (size_t)ti * DD + d);
    float4 a4 = *(const float4*)(ae + (size_t)ai * DD + d);
    float4 p4 = *(const float4*)(pe + (size_t)t  * DD + d);
    float4 o;
    o.x = 0.5f*(t4.x + a4.x) + p4.x;
    o.y = 0.5f*(t4.y + a4.y) + p4.y;
    o.z = 0.5f*(t4.z + a4.z) + p4.z;
    o.w = 0.5f*(t4.w + a4.w) + p4.w;
    *(float4*)(g_x + (size_t)token * DD + d) = o;
    __half2* x16 = (__half2*)(g_x16 + (size_t)token * DD + d);
    x16[0] = __floats2half2_rn(o.x, o.y);
    x16[1] = __floats2half2_rn(o.z, o.w);
}

// ---------------------------------------------------------------------------
__global__ void permute_wqkv(const float* __restrict__ W, const float* __restrict__ bias) {
    int n = blockIdx.x * 256 + threadIdx.x;
    int k = blockIdx.y;
    int wh = n >> 9, rem = n & 511;
    int h = rem >> 6, dh = rem & 63;
    int o = h * 192 + dh * 3 + wh;
    g_wp[(size_t)k * (3*DD) + n] = W[(size_t)k * (3*DD) + o];
    if (k == 0) g_bp[n] = bias[o];
}

// W [K,N] fp32 row-major -> Wt16 [N,K] fp16. grid (K/32, N/32), block (32,8)
__global__ void transpose_h(const float* __restrict__ W, __half* __restrict__ Wt,
                            int K, int N) {
    __shared__ float t[32][33];
    int k0 = blockIdx.x * 32, n0 = blockIdx.y * 32;
    int tx = threadIdx.x, ty = threadIdx.y;
#pragma unroll
    for (int i = 0; i < 32; i += 8)
        t[ty + i][tx] = W[(size_t)(k0 + ty + i) * N + n0 + tx];
    __syncthreads();
#pragma unroll
    for (int i = 0; i < 32; i += 8)
        Wt[(size_t)(n0 + ty + i) * K + k0 + tx] = __float2half(t[tx][ty + i]);
}

// ---------------------------------------------------------------------------
// fp16 GEMM: C[M,N] = A16[M,K] @ Bt16[N,K]^T + bias.
// 128x128 tile, BK=64, cp.async double-buffer, 8 warps, warp tile 32x64,
// m16n8k16 mma. MODE: 0 fp32 out, 1 fp16 out + ReLU, 2 planar QKV fp32 out.
// smem row pitch 144B (36 words: 32 data half2 + 4 pad) -> conflict-free frags
// ---------------------------------------------------------------------------
#define HROW 144                      // bytes per smem row (64 halves + pad)
#define HSTAGE (256 * HROW)           // A(128 rows) + B(128 rows)
#define GEMM_SMEM (2 * HSTAGE)

template<int MODE>
__global__ __launch_bounds__(256, 2)
void gemm_h(const __half* __restrict__ A, const __half* __restrict__ Bt,
            const float* __restrict__ bias, void* __restrict__ Cout,
            int N, int K) {
    extern __shared__ char smc[];
    uint32_t sb = smem_u32(smc);

    int tid = threadIdx.x;
    int wid = tid >> 5, lane = tid & 31;
    int g = lane >> 2, tc = lane & 3;
    int wm0 = (wid & 3) * 32, wn0 = (wid >> 2) * 64;
    int m0 = blockIdx.y * 128, n0 = blockIdx.x * 128;

    int lrow = tid >> 1;                // 0..127
    int lch  = (tid & 1) * 4;           // chunk base 0 or 4 (16B chunks of 8 halves)

    const __half* Arow = A  + (size_t)(m0 + lrow) * K + lch * 8;
    const __half* Brow = Bt + (size_t)(n0 + lrow) * K + lch * 8;
    uint32_t dA = sb + lrow * HROW + lch * 16;
    uint32_t dB = dA + 128 * HROW;

    float acc[2][8][4];
#pragma unroll
    for (int mf = 0; mf < 2; mf++)
#pragma unroll
        for (int nf = 0; nf < 8; nf++)
#pragma unroll
            for (int e = 0; e < 4; e++) acc[mf][nf][e] = 0.f;

    int nchunk = K >> 6;

    // prologue: stage 0
#pragma unroll
    for (int i = 0; i < 4; i++) {
        cp16(dA + i*16, Arow + i*8);
        cp16(dB + i*16, Brow + i*8);
    }
    CP_COMMIT();

    for (int c = 0; c < nchunk; c++) {
        if (c + 1 < nchunk) {
            uint32_t st = ((c + 1) & 1) * HSTAGE;
            const __half* An = Arow + (size_t)(c + 1) * 64;
            const __half* Bn = Brow + (size_t)(c + 1) * 64;
#pragma unroll
            for (int i = 0; i < 4; i++) {
                cp16(dA + st + i*16, An + i*8);
                cp16(dB + st + i*16, Bn + i*8);
            }
            CP_COMMIT();
            CP_WAIT(1);
        } else {
            CP_WAIT(0);
        }
        __syncthreads();

        const uint32_t* As = (const uint32_t*)(smc + (c & 1) * HSTAGE);
        const uint32_t* Bs = As + 128 * 36;
#pragma unroll
        for (int ks = 0; ks < 4; ks++) {
            int kk2 = ks * 8;
            uint32_t a[2][4];
#pragma unroll
            for (int mf = 0; mf < 2; mf++) {
                const uint32_t* r0 = As + (wm0 + mf*16 + g) * 36 + kk2 + tc;
                const uint32_t* r1 = r0 + 8 * 36;
                a[mf][0] = r0[0];
                a[mf][1] = r1[0];
                a[mf][2] = r0[4];
                a[mf][3] = r1[4];
            }
#pragma unroll
            for (int nf = 0; nf < 8; nf++) {
                const uint32_t* br = Bs + (wn0 + nf*8 + g) * 36 + kk2 + tc;
                uint32_t b0 = br[0], b1 = br[4];
                mma16h(acc[0][nf], a[0], b0, b1);
                mma16h(acc[1][nf], a[1], b0, b1);
            }
        }
        __syncthreads();   // all warps done with stage (c&1) before refill at c+2
    }

    // ---- epilogue ----
#pragma unroll
    for (int mf = 0; mf < 2; mf++) {
#pragma unroll
        for (int half = 0; half < 2; half++) {
            int row = m0 + wm0 + mf*16 + g + half*8;
#pragma unroll
            for (int nf = 0; nf < 8; nf++) {
                int col = n0 + wn0 + nf*8 + tc*2;
                float v0 = acc[mf][nf][half*2 + 0] + bias[col];
                float v1 = acc[mf][nf][half*2 + 1] + bias[col + 1];
                if (MODE == 1) {
                    v0 = fmaxf(v0, 0.f); v1 = fmaxf(v1, 0.f);
                    __half2* C = (__half2*)Cout;
                    C[((size_t)row * N + col) >> 1] = __floats2half2_rn(v0, v1);
                } else if (MODE == 2) {
                    int b = row >> 9, t = row & 511;
                    int wh = col >> 9, rem = col & 511;
                    int h = rem >> 6, dh = rem & 63;
                    float* dst = (float*)Cout + (size_t)wh * PLANE
                               + (((size_t)(b*HH + h)) * TT + t) * DH + dh;
                    *(float2*)dst = make_float2(v0, v1);
                } else {
                    *(float2*)((float*)Cout + (size_t)row * N + col) = make_float2(v0, v1);
                }
            }
        }
    }
}

// ---------------------------------------------------------------------------
// Tensor-core flash attention (round 3, unchanged; tf32 mma)
// ---------------------------------------------------------------------------
#define QS_W (128*68)
#define KS_W (64*68)
#define VS_W (64*68)
#define ATT_SMEM ((QS_W + KS_W + VS_W + 64) * 4)

__global__ __launch_bounds__(256, 2)
void attn_kernel(const float* __restrict__ qkv, const int* __restrict__ track_ids,
                 float* __restrict__ y) {
    extern __shared__ uint32_t sma[];
    uint32_t* Qs = sma;
    uint32_t* Ks = Qs + QS_W;
    uint32_t* Vs = Ks + KS_W;
    float*    padsm = (float*)(Vs + VS_W);

    int tid = threadIdx.x;
    int wid = tid >> 5, lane = tid & 31;
    int g = lane >> 2, tc = lane & 3;
    int bh = blockIdx.x;
    int b = bh >> 3, h = bh & 7;
    int q0 = blockIdx.y * 128;
    int wq0 = wid * 16;

    const float* qpl = qkv;
    const float* kpl = qkv + PLANE;
    const float* vpl = qkv + 2 * PLANE;
    size_t hb = ((size_t)(b*HH + h)) * TT * DH;

    {
        int r = tid >> 4, c4 = (tid & 15) * 4;
#pragma unroll
        for (int it = 0; it < 8; it++) {
            int row = r + it * 16;
            float4 v = *(const float4*)(qpl + hb + (size_t)(q0 + row) * DH + c4);
            uint32_t* p = Qs + row * 68 + c4;
            p[0] = f2tf32(v.x * 0.125f); p[1] = f2tf32(v.y * 0.125f);
            p[2] = f2tf32(v.z * 0.125f); p[3] = f2tf32(v.w * 0.125f);
        }
    }

    float o_acc[8][4];
#pragma unroll
    for (int vf = 0; vf < 8; vf++)
#pragma unroll
        for (int e = 0; e < 4; e++) o_acc[vf][e] = 0.f;
    float m0r = -1e30f, m1r = -1e30f, l0r = 0.f, l1r = 0.f;

    int q_r0 = q0 + wq0 + g;
    int q_r1 = q_r0 + 8;
    int causal_tiles = (blockIdx.y + 1) * 2;

    for (int kt = 0; kt < TT/64; kt++) {
        if (kt >= causal_tiles) {
            if (__syncthreads_and(m0r > -5000.f && m1r > -5000.f)) break;
        }
        __syncthreads();
        {
            int r = tid >> 4, c4 = (tid & 15) * 4;
#pragma unroll
            for (int it = 0; it < 4; it++) {
                int row = r + it * 16;
                float4 kv4 = *(const float4*)(kpl + hb + (size_t)(kt*64 + row) * DH + c4);
                float4 vv4 = *(const float4*)(vpl + hb + (size_t)(kt*64 + row) * DH + c4);
                uint32_t* pk = Ks + row * 68 + c4;
                uint32_t* pv = Vs + row * 68 + c4;
                pk[0] = f2tf32(kv4.x); pk[1] = f2tf32(kv4.y);
                pk[2] = f2tf32(kv4.z); pk[3] = f2tf32(kv4.w);
                pv[0] = f2tf32(vv4.x); pv[1] = f2tf32(vv4.y);
                pv[2] = f2tf32(vv4.z); pv[3] = f2tf32(vv4.w);
            }
            if (tid < 64)
                padsm[tid] = (track_ids[b * TT + kt*64 + tid] != 0) ? 1.f : 0.f;
        }
        __syncthreads();

        float sacc[8][4];
#pragma unroll
        for (int nf = 0; nf < 8; nf++)
#pragma unroll
            for (int e = 0; e < 4; e++) sacc[nf][e] = 0.f;
#pragma unroll
        for (int ks = 0; ks < 8; ks++) {
            int kk = ks * 8;
            uint32_t a[4];
            const uint32_t* r0 = Qs + (wq0 + g) * 68 + kk + tc;
            const uint32_t* r1 = r0 + 8 * 68;
            a[0] = r0[0]; a[1] = r1[0]; a[2] = r0[4]; a[3] = r1[4];
#pragma unroll
            for (int nf = 0; nf < 8; nf++) {
                const uint32_t* kr = Ks + (nf*8 + g) * 68 + kk + tc;
                mma8(sacc[nf], a, kr[0], kr[4]);
            }
        }

        float tmax0 = -1e30f, tmax1 = -1e30f;
#pragma unroll
        for (int nf = 0; nf < 8; nf++) {
            int kcol = kt*64 + nf*8 + tc*2;
#pragma unroll
            for (int e = 0; e < 2; e++) {
                int key = kcol + e;
                float pad = padsm[key - kt*64];
                float s0 = sacc[nf][e]   + ((key <= q_r0 && pad != 0.f) ? 0.f : -10000.f);
                float s1 = sacc[nf][e+2] + ((key <= q_r1 && pad != 0.f) ? 0.f : -10000.f);
                sacc[nf][e] = s0; sacc[nf][e+2] = s1;
                tmax0 = fmaxf(tmax0, s0);
                tmax1 = fmaxf(tmax1, s1);
            }
        }
        tmax0 = fmaxf(tmax0, __shfl_xor_sync(0xffffffffu, tmax0, 1));
        tmax0 = fmaxf(tmax0, __shfl_xor_sync(0xffffffffu, tmax0, 2));
        tmax1 = fmaxf(tmax1, __shfl_xor_sync(0xffffffffu, tmax1, 1));
        tmax1 = fmaxf(tmax1, __shfl_xor_sync(0xffffffffu, tmax1, 2));

        float mn0 = fmaxf(m0r, tmax0), mn1 = fmaxf(m1r, tmax1);
        float c0 = __expf(m0r - mn0),  c1 = __expf(m1r - mn1);
        m0r = mn0; m1r = mn1;

        float ls0 = 0.f, ls1 = 0.f;
#pragma unroll
        for (int nf = 0; nf < 8; nf++) {
#pragma unroll
            for (int e = 0; e < 2; e++) {
                float p0 = __expf(sacc[nf][e]   - mn0);
                float p1 = __expf(sacc[nf][e+2] - mn1);
                ls0 += p0; ls1 += p1;
                sacc[nf][e]   = __uint_as_float(f2tf32(p0));
                sacc[nf][e+2] = __uint_as_float(f2tf32(p1));
            }
        }
        ls0 += __shfl_xor_sync(0xffffffffu, ls0, 1);
        ls0 += __shfl_xor_sync(0xffffffffu, ls0, 2);
        ls1 += __shfl_xor_sync(0xffffffffu, ls1, 1);
        ls1 += __shfl_xor_sync(0xffffffffu, ls1, 2);
        l0r = l0r * c0 + ls0;
        l1r = l1r * c1 + ls1;

#pragma unroll
        for (int vf = 0; vf < 8; vf++) {
            o_acc[vf][0] *= c0; o_acc[vf][1] *= c0;
            o_acc[vf][2] *= c1; o_acc[vf][3] *= c1;
        }

        int sl1 = (lane & 28) | (tc >> 1);
        int sl2 = sl1 + 2;
        bool odd = (tc & 1);
#pragma unroll
        for (int ks = 0; ks < 8; ks++) {
            float p00 = __shfl_sync(0xffffffffu, sacc[ks][0], sl1);
            float p01 = __shfl_sync(0xffffffffu, sacc[ks][1], sl1);
            float p02 = __shfl_sync(0xffffffffu, sacc[ks][2], sl1);
            float p03 = __shfl_sync(0xffffffffu, sacc[ks][3], sl1);
            float p10 = __shfl_sync(0xffffffffu, sacc[ks][0], sl2);
            float p11 = __shfl_sync(0xffffffffu, sacc[ks][1], sl2);
            float p12 = __shfl_sync(0xffffffffu, sacc[ks][2], sl2);
            float p13 = __shfl_sync(0xffffffffu, sacc[ks][3], sl2);
            uint32_t a[4];
            a[0] = __float_as_uint(odd ? p01 : p00);
            a[1] = __float_as_uint(odd ? p03 : p02);
            a[2] = __float_as_uint(odd ? p11 : p10);
            a[3] = __float_as_uint(odd ? p13 : p12);
            const uint32_t* v0 = Vs + (ks*8 + tc) * 68 + g;
            const uint32_t* v1 = v0 + 4 * 68;
#pragma unroll
            for (int vf = 0; vf < 8; vf++)
                mma8(o_acc[vf], a, v0[vf*8], v1[vf*8]);
        }
    }

    float inv0 = 1.f / l0r, inv1 = 1.f / l1r;
    float* y0 = y + (size_t)(b * TT + q_r0) * DD + h * DH;
    float* y1 = y + (size_t)(b * TT + q_r1) * DD + h * DH;
#pragma unroll
    for (int vf = 0; vf < 8; vf++) {
        int dh = vf*8 + tc*2;
        *(float2*)(y0 + dh) = make_float2(o_acc[vf][0] * inv0, o_acc[vf][1] * inv0);
        *(float2*)(y1 + dh) = make_float2(o_acc[vf][2] * inv1, o_acc[vf][3] * inv1);
    }
}

// ---------------------------------------------------------------------------
// Fused residual + LayerNorm; also emits fp16 copy for the next GEMM's A.
// ---------------------------------------------------------------------------
__global__ void add_ln_kernel(const float* __restrict__ x, const float* __restrict__ y,
                              const float* __restrict__ g, const float* __restrict__ b,
                              float* __restrict__ out, __half* __restrict__ out16) {
    int token = blockIdx.x * 8 + (threadIdx.x >> 5);
    int lane = threadIdx.x & 31;
    const float4* xr = (const float4*)(x + (size_t)token * DD);
    const float4* yr = (const float4*)(y + (size_t)token * DD);

    float4 v[4];
    float s = 0.f;
#pragma unroll
    for (int c = 0; c < 4; c++) {
        float4 a = xr[lane + 32*c];
        float4 w = yr[lane + 32*c];
        v[c].x = a.x + w.x; v[c].y = a.y + w.y;
        v[c].z = a.z + w.z; v[c].w = a.w + w.w;
        s += v[c].x + v[c].y + v[c].z + v[c].w;
    }
#pragma unroll
    for (int off = 16; off; off >>= 1) s += __shfl_xor_sync(0xffffffffu, s, off);
    float mu = s * (1.f / 512.f);

    float sq = 0.f;
#pragma unroll
    for (int c = 0; c < 4; c++) {
        float dx = v[c].x - mu, dy = v[c].y - mu, dz = v[c].z - mu, dw = v[c].w - mu;
        sq += dx*dx + dy*dy + dz*dz + dw*dw;
    }
#pragma unroll
    for (int off = 16; off; off >>= 1) sq += __shfl_xor_sync(0xffffffffu, sq, off);
    float r = rsqrtf(sq * (1.f / 512.f) + 1e-5f);

    const float4* g4 = (const float4*)g;
    const float4* b4 = (const float4*)b;
    float4* orow = (float4*)(out + (size_t)token * DD);
    __half2* o16 = (__half2*)(out16 + (size_t)token * DD);
#pragma unroll
    for (int c = 0; c < 4; c++) {
        int idx = lane + 32*c;
        float4 gg = g4[idx], bb = b4[idx];
        float4 o;
        o.x = (v[c].x - mu) * r * gg.x + bb.x;
        o.y = (v[c].y - mu) * r * gg.y + bb.y;
        o.z = (v[c].z - mu) * r * gg.z + bb.z;
        o.w = (v[c].w - mu) * r * gg.w + bb.w;
        orow[idx] = o;
        o16[idx*2 + 0] = __floats2half2_rn(o.x, o.y);
        o16[idx*2 + 1] = __floats2half2_rn(o.z, o.w);
    }
}

// ---------------------------------------------------------------------------
extern "C" void kernel_launch(void* const* d_in, const int* in_sizes, int n_in,
                              void* d_out, int out_size) {
    const int*   track_ids  = (const int*)  d_in[0];
    const int*   artist_ids = (const int*)  d_in[1];
    const float* track_emb  = (const float*)d_in[2];
    const float* artist_emb = (const float*)d_in[3];
    const float* pos_emb    = (const float*)d_in[4];
    const float* Wqkv       = (const float*)d_in[5];
    const float* bqkv       = (const float*)d_in[6];
    const float* Wff        = (const float*)d_in[7];
    const float* bff        = (const float*)d_in[8];
    const float* Wout       = (const float*)d_in[9];
    const float* bout       = (const float*)d_in[10];
    const float* g1         = (const float*)d_in[11];
    const float* b1         = (const float*)d_in[12];
    const float* g2         = (const float*)d_in[13];
    const float* b2         = (const float*)d_in[14];
    float* out = (float*)d_out;

    float *x, *qkv, *y, *wp, *bp;
    __half *x16, *h16, *wt16;
    cudaGetSymbolAddress((void**)&x,    g_x);
    cudaGetSymbolAddress((void**)&x16,  g_x16);
    cudaGetSymbolAddress((void**)&qkv,  g_qkv);
    cudaGetSymbolAddress((void**)&y,    g_y);
    cudaGetSymbolAddress((void**)&h16,  g_h16);
    cudaGetSymbolAddress((void**)&wp,   g_wp);
    cudaGetSymbolAddress((void**)&bp,   g_bp);
    cudaGetSymbolAddress((void**)&wt16, g_wt16);

    cudaFuncSetAttribute(gemm_h<0>, cudaFuncAttributeMaxDynamicSharedMemorySize, GEMM_SMEM);
    cudaFuncSetAttribute(gemm_h<1>, cudaFuncAttributeMaxDynamicSharedMemorySize, GEMM_SMEM);
    cudaFuncSetAttribute(gemm_h<2>, cudaFuncAttributeMaxDynamicSharedMemorySize, GEMM_SMEM);
    cudaFuncSetAttribute(attn_kernel, cudaFuncAttributeMaxDynamicSharedMemorySize, ATT_SMEM);

    embed_kernel<<<NTOK, 128>>>(track_ids, artist_ids, track_emb, artist_emb, pos_emb);

    for (int i = 0; i < LL; i++) {
        // --- QKV
        permute_wqkv<<<dim3(6, 512), 256>>>(Wqkv + (size_t)i * DD * (3*DD),
                                            bqkv + (size_t)i * (3*DD));
        transpose_h<<<dim3(DD/32, (3*DD)/32), dim3(32, 8)>>>(wp, wt16, DD, 3*DD);
        gemm_h<2><<<dim3((3*DD)/128, NTOK/128), 256, GEMM_SMEM>>>(
            x16, wt16, bp, qkv, 3*DD, DD);
        attn_kernel<<<dim3(BB*HH, 4), 256, ATT_SMEM>>>(qkv, track_ids, y);
        add_ln_kernel<<<NTOK/8, 256>>>(x, y, g1 + (size_t)i*DD, b1 + (size_t)i*DD, x, x16);
        // --- FF1 (fp16 hidden + ReLU)
        transpose_h<<<dim3(DD/32, DFF/32), dim3(32, 8)>>>(
            Wff + (size_t)i * DD * DFF, wt16, DD, DFF);
        gemm_h<1><<<dim3(DFF/128, NTOK/128), 256, GEMM_SMEM>>>(
            x16, wt16, bff + (size_t)i * DFF, h16, DFF, DD);
        // --- FF2
        transpose_h<<<dim3(DFF/32, DD/32), dim3(32, 8)>>>(
            Wout + (size_t)i * DFF * DD, wt16, DFF, DD);
        gemm_h<0><<<dim3(DD/128, NTOK/128), 256, GEMM_SMEM>>>(
            h16, wt16, bout + (size_t)i * DD, y, DD, DFF);
        add_ln_kernel<<<NTOK/8, 256>>>(x, y, g2 + (size_t)i*DD, b2 + (size_t)i*DD,
                                       (i == LL-1) ? out : x, x16);
    }
}

// round 7
// speedup vs baseline: 4.9084x; 1.0643x over previous
#include <cuda_runtime.h>
#include <cuda_fp16.h>
#include <cstdint>

// ---------------------------------------------------------------------------
// Decoder: 6-layer transformer, B=32, T=512, D=512 (H=8, Dh=64), DFF=2048
// Round 6: fp16 GEMMs with ldmatrix fragments + 3-stage cp.async pipeline
// ---------------------------------------------------------------------------

#define BB   32
#define TT   512
#define HH   8
#define DH   64
#define DD   512
#define DFF  2048
#define LL   6
#define NTOK (BB*TT)
#define PLANE ((size_t)NTOK * DD)

__device__ float  g_x   [(size_t)NTOK * DD];
__device__ __half g_x16 [(size_t)NTOK * DD];
__device__ float  g_qkv [(size_t)NTOK * 3*DD];
__device__ float  g_y   [(size_t)NTOK * DD];
__device__ __half g_h16 [(size_t)NTOK * DFF];
__device__ float  g_bp  [3*DD];
__device__ __half g_wt16[(size_t)1 << 21];

__device__ __forceinline__ uint32_t f2tf32(float f) {
    uint32_t u;
    asm("cvt.rna.tf32.f32 %0, %1;" : "=r"(u) : "f"(f));
    return u;
}
__device__ __forceinline__ uint32_t smem_u32(const void* p) {
    uint32_t a;
    asm("{ .reg .u64 t; cvta.to.shared.u64 t, %1; cvt.u32.u64 %0, t; }" : "=r"(a) : "l"(p));
    return a;
}
__device__ __forceinline__ void mma8(float* c, const uint32_t* a, uint32_t b0, uint32_t b1) {
    asm volatile(
        "mma.sync.aligned.m16n8k8.row.col.f32.tf32.tf32.f32 "
        "{%0,%1,%2,%3}, {%4,%5,%6,%7}, {%8,%9}, {%0,%1,%2,%3};"
        : "+f"(c[0]), "+f"(c[1]), "+f"(c[2]), "+f"(c[3])
        : "r"(a[0]), "r"(a[1]), "r"(a[2]), "r"(a[3]), "r"(b0), "r"(b1));
}
__device__ __forceinline__ void mma16h(float* c, const uint32_t* a, uint32_t b0, uint32_t b1) {
    asm volatile(
        "mma.sync.aligned.m16n8k16.row.col.f32.f16.f16.f32 "
        "{%0,%1,%2,%3}, {%4,%5,%6,%7}, {%8,%9}, {%0,%1,%2,%3};"
        : "+f"(c[0]), "+f"(c[1]), "+f"(c[2]), "+f"(c[3])
        : "r"(a[0]), "r"(a[1]), "r"(a[2]), "r"(a[3]), "r"(b0), "r"(b1));
}
__device__ __forceinline__ void ldm_x4(uint32_t* r, uint32_t addr) {
    asm volatile("ldmatrix.sync.aligned.m8n8.x4.shared.b16 {%0,%1,%2,%3}, [%4];"
                 : "=r"(r[0]), "=r"(r[1]), "=r"(r[2]), "=r"(r[3]) : "r"(addr));
}
__device__ __forceinline__ void cp16(uint32_t dst, const void* src) {
    asm volatile("cp.async.cg.shared.global [%0], [%1], 16;" :: "r"(dst), "l"(src));
}
#define CP_COMMIT() asm volatile("cp.async.commit_group;" ::: "memory")
#define CP_WAIT(n)  asm volatile("cp.async.wait_group %0;" :: "n"(n) : "memory")

// ---------------------------------------------------------------------------
__global__ void embed_kernel(const int* __restrict__ tids, const int* __restrict__ aids,
                             const float* __restrict__ te, const float* __restrict__ ae,
                             const float* __restrict__ pe) {
    int token = blockIdx.x;
    int t = token & (TT - 1);
    int ti = tids[token], ai = aids[token];
    int d = threadIdx.x * 4;
    float4 t4 = *(const float4*)(te + (size_t)ti * DD + d);
    float4 a4 = *(const float4*)(ae + (size_t)ai * DD + d);
    float4 p4 = *(const float4*)(pe + (size_t)t  * DD + d);
    float4 o;
    o.x = 0.5f*(t4.x + a4.x) + p4.x;
    o.y = 0.5f*(t4.y + a4.y) + p4.y;
    o.z = 0.5f*(t4.z + a4.z) + p4.z;
    o.w = 0.5f*(t4.w + a4.w) + p4.w;
    *(float4*)(g_x + (size_t)token * DD + d) = o;
    __half2* x16 = (__half2*)(g_x16 + (size_t)token * DD + d);
    x16[0] = __floats2half2_rn(o.x, o.y);
    x16[1] = __floats2half2_rn(o.z, o.w);
}

// ---------------------------------------------------------------------------
// Fused QKV weight permute + transpose + fp16 convert:
// Wt16[n][k] = W[k][perm(n)], perm: n = wh*512+h*64+dh -> o = h*192+dh*3+wh.
// grid (DD/32, 3*DD/32), block (32,8)
// ---------------------------------------------------------------------------
__global__ void transpose_perm_h(const float* __restrict__ W, const float* __restrict__ bias,
                                 __half* __restrict__ Wt) {
    __shared__ float t[32][33];
    int k0 = blockIdx.x * 32, n0 = blockIdx.y * 32;
    int tx = threadIdx.x, ty = threadIdx.y;
    int n = n0 + tx;
    int wh = n >> 9, rem = n & 511;
    int h = rem >> 6, dh = rem & 63;
    int o = h * 192 + dh * 3 + wh;
#pragma unroll
    for (int i = 0; i < 32; i += 8)
        t[ty + i][tx] = W[(size_t)(k0 + ty + i) * (3*DD) + o];
    if (blockIdx.x == 0 && ty == 0) g_bp[n] = bias[o];
    __syncthreads();
#pragma unroll
    for (int i = 0; i < 32; i += 8)
        Wt[(size_t)(n0 + ty + i) * DD + k0 + tx] = __float2half(t[tx][ty + i]);
}

// W [K,N] fp32 -> Wt16 [N,K] fp16. grid (K/32, N/32), block (32,8)
__global__ void transpose_h(const float* __restrict__ W, __half* __restrict__ Wt,
                            int K, int N) {
    __shared__ float t[32][33];
    int k0 = blockIdx.x * 32, n0 = blockIdx.y * 32;
    int tx = threadIdx.x, ty = threadIdx.y;
#pragma unroll
    for (int i = 0; i < 32; i += 8)
        t[ty + i][tx] = W[(size_t)(k0 + ty + i) * N + n0 + tx];
    __syncthreads();
#pragma unroll
    for (int i = 0; i < 32; i += 8)
        Wt[(size_t)(n0 + ty + i) * K + k0 + tx] = __float2half(t[tx][ty + i]);
}

// ---------------------------------------------------------------------------
// fp16 GEMM: C[M,N] = A16[M,K] @ Bt16[N,K]^T + bias.
// 128x128 tile, BK=64, 3-stage cp.async, ldmatrix frags, m16n8k16 mma.
// MODE: 0 fp32 out, 1 fp16 out + ReLU, 2 planar QKV fp32 out.
// ---------------------------------------------------------------------------
#define HROW 144
#define HSTAGE (256 * HROW)
#define NSTAGE 3
#define GEMM_SMEM (NSTAGE * HSTAGE)

template<int MODE>
__global__ __launch_bounds__(256, 2)
void gemm_h(const __half* __restrict__ A, const __half* __restrict__ Bt,
            const float* __restrict__ bias, void* __restrict__ Cout,
            int N, int K) {
    extern __shared__ char smc[];
    uint32_t sb = smem_u32(smc);

    int tid = threadIdx.x;
    int wid = tid >> 5, lane = tid & 31;
    int g = lane >> 2, tc = lane & 3;
    int wm0 = (wid & 3) * 32, wn0 = (wid >> 2) * 64;
    int m0 = blockIdx.y * 128, n0 = blockIdx.x * 128;

    // cp.async loader mapping
    int lrow = tid >> 1;
    int lch  = (tid & 1) * 4;
    const __half* Arow = A  + (size_t)(m0 + lrow) * K + lch * 8;
    const __half* Brow = Bt + (size_t)(n0 + lrow) * K + lch * 8;
    uint32_t dA0 = sb + lrow * HROW + lch * 16;
    uint32_t dB0 = dA0 + 128 * HROW;

    // ldmatrix per-lane offsets
    uint32_t aoff[2], boff[4];
#pragma unroll
    for (int mf = 0; mf < 2; mf++)
        aoff[mf] = (uint32_t)((wm0 + mf*16 + (lane & 15)) * HROW + ((lane >> 4) & 1) * 16);
#pragma unroll
    for (int q = 0; q < 4; q++)
        boff[q] = (uint32_t)((wn0 + q*16 + (lane & 7) + ((lane & 16) ? 8 : 0)) * HROW
                             + ((lane & 8) ? 16 : 0)) + 128 * HROW;

    float acc[2][8][4];
#pragma unroll
    for (int mf = 0; mf < 2; mf++)
#pragma unroll
        for (int nf = 0; nf < 8; nf++)
#pragma unroll
            for (int e = 0; e < 4; e++) acc[mf][nf][e] = 0.f;

    int nchunk = K >> 6;

    // prologue: stages 0 and 1
#pragma unroll
    for (int s = 0; s < 2; s++) {
        uint32_t st = s * HSTAGE;
        const __half* An = Arow + (size_t)s * 64;
        const __half* Bn = Brow + (size_t)s * 64;
#pragma unroll
        for (int i = 0; i < 4; i++) {
            cp16(dA0 + st + i*16, An + i*8);
            cp16(dB0 + st + i*16, Bn + i*8);
        }
        CP_COMMIT();
    }

    for (int c = 0; c < nchunk; c++) {
        if (c + 2 <= nchunk) CP_WAIT(1); else CP_WAIT(0);
        __syncthreads();

        if (c + 2 < nchunk) {
            uint32_t st = (uint32_t)((c + 2) % NSTAGE) * HSTAGE;
            const __half* An = Arow + (size_t)(c + 2) * 64;
            const __half* Bn = Brow + (size_t)(c + 2) * 64;
#pragma unroll
            for (int i = 0; i < 4; i++) {
                cp16(dA0 + st + i*16, An + i*8);
                cp16(dB0 + st + i*16, Bn + i*8);
            }
            CP_COMMIT();
        }

        uint32_t stb = sb + (uint32_t)(c % NSTAGE) * HSTAGE;
#pragma unroll
        for (int ks = 0; ks < 4; ks++) {
            uint32_t koff = ks * 32;
            uint32_t a0[4], a1[4];
            ldm_x4(a0, stb + aoff[0] + koff);
            ldm_x4(a1, stb + aoff[1] + koff);
#pragma unroll
            for (int q = 0; q < 4; q++) {
                uint32_t bq[4];
                ldm_x4(bq, stb + boff[q] + koff);
                mma16h(acc[0][2*q],   a0, bq[0], bq[1]);
                mma16h(acc[1][2*q],   a1, bq[0], bq[1]);
                mma16h(acc[0][2*q+1], a0, bq[2], bq[3]);
                mma16h(acc[1][2*q+1], a1, bq[2], bq[3]);
            }
        }
    }

    // ---- epilogue ----
#pragma unroll
    for (int mf = 0; mf < 2; mf++) {
#pragma unroll
        for (int half = 0; half < 2; half++) {
            int row = m0 + wm0 + mf*16 + g + half*8;
#pragma unroll
            for (int nf = 0; nf < 8; nf++) {
                int col = n0 + wn0 + nf*8 + tc*2;
                float v0 = acc[mf][nf][half*2 + 0] + bias[col];
                float v1 = acc[mf][nf][half*2 + 1] + bias[col + 1];
                if (MODE == 1) {
                    v0 = fmaxf(v0, 0.f); v1 = fmaxf(v1, 0.f);
                    __half2* C = (__half2*)Cout;
                    C[((size_t)row * N + col) >> 1] = __floats2half2_rn(v0, v1);
                } else if (MODE == 2) {
                    int b = row >> 9, t = row & 511;
                    int wh = col >> 9, rem = col & 511;
                    int h = rem >> 6, dh = rem & 63;
                    float* dst = (float*)Cout + (size_t)wh * PLANE
                               + (((size_t)(b*HH + h)) * TT + t) * DH + dh;
                    *(float2*)dst = make_float2(v0, v1);
                } else {
                    *(float2*)((float*)Cout + (size_t)row * N + col) = make_float2(v0, v1);
                }
            }
        }
    }
}

// ---------------------------------------------------------------------------
// Tensor-core flash attention (tf32 mma, unchanged)
// ---------------------------------------------------------------------------
#define QS_W (128*68)
#define KS_W (64*68)
#define VS_W (64*68)
#define ATT_SMEM ((QS_W + KS_W + VS_W + 64) * 4)

__global__ __launch_bounds__(256, 2)
void attn_kernel(const float* __restrict__ qkv, const int* __restrict__ track_ids,
                 float* __restrict__ y) {
    extern __shared__ uint32_t sma[];
    uint32_t* Qs = sma;
    uint32_t* Ks = Qs + QS_W;
    uint32_t* Vs = Ks + KS_W;
    float*    padsm = (float*)(Vs + VS_W);

    int tid = threadIdx.x;
    int wid = tid >> 5, lane = tid & 31;
    int g = lane >> 2, tc = lane & 3;
    int bh = blockIdx.x;
    int b = bh >> 3, h = bh & 7;
    int q0 = blockIdx.y * 128;
    int wq0 = wid * 16;

    const float* qpl = qkv;
    const float* kpl = qkv + PLANE;
    const float* vpl = qkv + 2 * PLANE;
    size_t hb = ((size_t)(b*HH + h)) * TT * DH;

    {
        int r = tid >> 4, c4 = (tid & 15) * 4;
#pragma unroll
        for (int it = 0; it < 8; it++) {
            int row = r + it * 16;
            float4 v = *(const float4*)(qpl + hb + (size_t)(q0 + row) * DH + c4);
            uint32_t* p = Qs + row * 68 + c4;
            p[0] = f2tf32(v.x * 0.125f); p[1] = f2tf32(v.y * 0.125f);
            p[2] = f2tf32(v.z * 0.125f); p[3] = f2tf32(v.w * 0.125f);
        }
    }

    float o_acc[8][4];
#pragma unroll
    for (int vf = 0; vf < 8; vf++)
#pragma unroll
        for (int e = 0; e < 4; e++) o_acc[vf][e] = 0.f;
    float m0r = -1e30f, m1r = -1e30f, l0r = 0.f, l1r = 0.f;

    int q_r0 = q0 + wq0 + g;
    int q_r1 = q_r0 + 8;
    int causal_tiles = (blockIdx.y + 1) * 2;

    for (int kt = 0; kt < TT/64; kt++) {
        if (kt >= causal_tiles) {
            if (__syncthreads_and(m0r > -5000.f && m1r > -5000.f)) break;
        }
        __syncthreads();
        {
            int r = tid >> 4, c4 = (tid & 15) * 4;
#pragma unroll
            for (int it = 0; it < 4; it++) {
                int row = r + it * 16;
                float4 kv4 = *(const float4*)(kpl + hb + (size_t)(kt*64 + row) * DH + c4);
                float4 vv4 = *(const float4*)(vpl + hb + (size_t)(kt*64 + row) * DH + c4);
                uint32_t* pk = Ks + row * 68 + c4;
                uint32_t* pv = Vs + row * 68 + c4;
                pk[0] = f2tf32(kv4.x); pk[1] = f2tf32(kv4.y);
                pk[2] = f2tf32(kv4.z); pk[3] = f2tf32(kv4.w);
                pv[0] = f2tf32(vv4.x); pv[1] = f2tf32(vv4.y);
                pv[2] = f2tf32(vv4.z); pv[3] = f2tf32(vv4.w);
            }
            if (tid < 64)
                padsm[tid] = (track_ids[b * TT + kt*64 + tid] != 0) ? 1.f : 0.f;
        }
        __syncthreads();

        float sacc[8][4];
#pragma unroll
        for (int nf = 0; nf < 8; nf++)
#pragma unroll
            for (int e = 0; e < 4; e++) sacc[nf][e] = 0.f;
#pragma unroll
        for (int ks = 0; ks < 8; ks++) {
            int kk = ks * 8;
            uint32_t a[4];
            const uint32_t* r0 = Qs + (wq0 + g) * 68 + kk + tc;
            const uint32_t* r1 = r0 + 8 * 68;
            a[0] = r0[0]; a[1] = r1[0]; a[2] = r0[4]; a[3] = r1[4];
#pragma unroll
            for (int nf = 0; nf < 8; nf++) {
                const uint32_t* kr = Ks + (nf*8 + g) * 68 + kk + tc;
                mma8(sacc[nf], a, kr[0], kr[4]);
            }
        }

        float tmax0 = -1e30f, tmax1 = -1e30f;
#pragma unroll
        for (int nf = 0; nf < 8; nf++) {
            int kcol = kt*64 + nf*8 + tc*2;
#pragma unroll
            for (int e = 0; e < 2; e++) {
                int key = kcol + e;
                float pad = padsm[key - kt*64];
                float s0 = sacc[nf][e]   + ((key <= q_r0 && pad != 0.f) ? 0.f : -10000.f);
                float s1 = sacc[nf][e+2] + ((key <= q_r1 && pad != 0.f) ? 0.f : -10000.f);
                sacc[nf][e] = s0; sacc[nf][e+2] = s1;
                tmax0 = fmaxf(tmax0, s0);
                tmax1 = fmaxf(tmax1, s1);
            }
        }
        tmax0 = fmaxf(tmax0, __shfl_xor_sync(0xffffffffu, tmax0, 1));
        tmax0 = fmaxf(tmax0, __shfl_xor_sync(0xffffffffu, tmax0, 2));
        tmax1 = fmaxf(tmax1, __shfl_xor_sync(0xffffffffu, tmax1, 1));
        tmax1 = fmaxf(tmax1, __shfl_xor_sync(0xffffffffu, tmax1, 2));

        float mn0 = fmaxf(m0r, tmax0), mn1 = fmaxf(m1r, tmax1);
        float c0 = __expf(m0r - mn0),  c1 = __expf(m1r - mn1);
        m0r = mn0; m1r = mn1;

        float ls0 = 0.f, ls1 = 0.f;
#pragma unroll
        for (int nf = 0; nf < 8; nf++) {
#pragma unroll
            for (int e = 0; e < 2; e++) {
                float p0 = __expf(sacc[nf][e]   - mn0);
                float p1 = __expf(sacc[nf][e+2] - mn1);
                ls0 += p0; ls1 += p1;
                sacc[nf][e]   = __uint_as_float(f2tf32(p0));
                sacc[nf][e+2] = __uint_as_float(f2tf32(p1));
            }
        }
        ls0 += __shfl_xor_sync(0xffffffffu, ls0, 1);
        ls0 += __shfl_xor_sync(0xffffffffu, ls0, 2);
        ls1 += __shfl_xor_sync(0xffffffffu, ls1, 1);
        ls1 += __shfl_xor_sync(0xffffffffu, ls1, 2);
        l0r = l0r * c0 + ls0;
        l1r = l1r * c1 + ls1;

#pragma unroll
        for (int vf = 0; vf < 8; vf++) {
            o_acc[vf][0] *= c0; o_acc[vf][1] *= c0;
            o_acc[vf][2] *= c1; o_acc[vf][3] *= c1;
        }

        int sl1 = (lane & 28) | (tc >> 1);
        int sl2 = sl1 + 2;
        bool odd = (tc & 1);
#pragma unroll
        for (int ks = 0; ks < 8; ks++) {
            float p00 = __shfl_sync(0xffffffffu, sacc[ks][0], sl1);
            float p01 = __shfl_sync(0xffffffffu, sacc[ks][1], sl1);
            float p02 = __shfl_sync(0xffffffffu, sacc[ks][2], sl1);
            float p03 = __shfl_sync(0xffffffffu, sacc[ks][3], sl1);
            float p10 = __shfl_sync(0xffffffffu, sacc[ks][0], sl2);
            float p11 = __shfl_sync(0xffffffffu, sacc[ks][1], sl2);
            float p12 = __shfl_sync(0xffffffffu, sacc[ks][2], sl2);
            float p13 = __shfl_sync(0xffffffffu, sacc[ks][3], sl2);
            uint32_t a[4];
            a[0] = __float_as_uint(odd ? p01 : p00);
            a[1] = __float_as_uint(odd ? p03 : p02);
            a[2] = __float_as_uint(odd ? p11 : p10);
            a[3] = __float_as_uint(odd ? p13 : p12);
            const uint32_t* v0 = Vs + (ks*8 + tc) * 68 + g;
            const uint32_t* v1 = v0 + 4 * 68;
#pragma unroll
            for (int vf = 0; vf < 8; vf++)
                mma8(o_acc[vf], a, v0[vf*8], v1[vf*8]);
        }
    }

    float inv0 = 1.f / l0r, inv1 = 1.f / l1r;
    float* y0 = y + (size_t)(b * TT + q_r0) * DD + h * DH;
    float* y1 = y + (size_t)(b * TT + q_r1) * DD + h * DH;
#pragma unroll
    for (int vf = 0; vf < 8; vf++) {
        int dh = vf*8 + tc*2;
        *(float2*)(y0 + dh) = make_float2(o_acc[vf][0] * inv0, o_acc[vf][1] * inv0);
        *(float2*)(y1 + dh) = make_float2(o_acc[vf][2] * inv1, o_acc[vf][3] * inv1);
    }
}

// ---------------------------------------------------------------------------
__global__ void add_ln_kernel(const float* __restrict__ x, const float* __restrict__ y,
                              const float* __restrict__ g, const float* __restrict__ b,
                              float* __restrict__ out, __half* __restrict__ out16) {
    int token = blockIdx.x * 8 + (threadIdx.x >> 5);
    int lane = threadIdx.x & 31;
    const float4* xr = (const float4*)(x + (size_t)token * DD);
    const float4* yr = (const float4*)(y + (size_t)token * DD);

    float4 v[4];
    float s = 0.f;
#pragma unroll
    for (int c = 0; c < 4; c++) {
        float4 a = xr[lane + 32*c];
        float4 w = yr[lane + 32*c];
        v[c].x = a.x + w.x; v[c].y = a.y + w.y;
        v[c].z = a.z + w.z; v[c].w = a.w + w.w;
        s += v[c].x + v[c].y + v[c].z + v[c].w;
    }
#pragma unroll
    for (int off = 16; off; off >>= 1) s += __shfl_xor_sync(0xffffffffu, s, off);
    float mu = s * (1.f / 512.f);

    float sq = 0.f;
#pragma unroll
    for (int c = 0; c < 4; c++) {
        float dx = v[c].x - mu, dy = v[c].y - mu, dz = v[c].z - mu, dw = v[c].w - mu;
        sq += dx*dx + dy*dy + dz*dz + dw*dw;
    }
#pragma unroll
    for (int off = 16; off; off >>= 1) sq += __shfl_xor_sync(0xffffffffu, sq, off);
    float r = rsqrtf(sq * (1.f / 512.f) + 1e-5f);

    const float4* g4 = (const float4*)g;
    const float4* b4 = (const float4*)b;
    float4* orow = (float4*)(out + (size_t)token * DD);
    __half2* o16 = (__half2*)(out16 + (size_t)token * DD);
#pragma unroll
    for (int c = 0; c < 4; c++) {
        int idx = lane + 32*c;
        float4 gg = g4[idx], bb = b4[idx];
        float4 o;
        o.x = (v[c].x - mu) * r * gg.x + bb.x;
        o.y = (v[c].y - mu) * r * gg.y + bb.y;
        o.z = (v[c].z - mu) * r * gg.z + bb.z;
        o.w = (v[c].w - mu) * r * gg.w + bb.w;
        orow[idx] = o;
        o16[idx*2 + 0] = __floats2half2_rn(o.x, o.y);
        o16[idx*2 + 1] = __floats2half2_rn(o.z, o.w);
    }
}

// ---------------------------------------------------------------------------
extern "C" void kernel_launch(void* const* d_in, const int* in_sizes, int n_in,
                              void* d_out, int out_size) {
    const int*   track_ids  = (const int*)  d_in[0];
    const int*   artist_ids = (const int*)  d_in[1];
    const float* track_emb  = (const float*)d_in[2];
    const float* artist_emb = (const float*)d_in[3];
    const float* pos_emb    = (const float*)d_in[4];
    const float* Wqkv       = (const float*)d_in[5];
    const float* bqkv       = (const float*)d_in[6];
    const float* Wff        = (const float*)d_in[7];
    const float* bff        = (const float*)d_in[8];
    const float* Wout       = (const float*)d_in[9];
    const float* bout       = (const float*)d_in[10];
    const float* g1         = (const float*)d_in[11];
    const float* b1         = (const float*)d_in[12];
    const float* g2         = (const float*)d_in[13];
    const float* b2         = (const float*)d_in[14];
    float* out = (float*)d_out;

    float *x, *qkv, *y, *bp;
    __half *x16, *h16, *wt16;
    cudaGetSymbolAddress((void**)&x,    g_x);
    cudaGetSymbolAddress((void**)&x16,  g_x16);
    cudaGetSymbolAddress((void**)&qkv,  g_qkv);
    cudaGetSymbolAddress((void**)&y,    g_y);
    cudaGetSymbolAddress((void**)&h16,  g_h16);
    cudaGetSymbolAddress((void**)&bp,   g_bp);
    cudaGetSymbolAddress((void**)&wt16, g_wt16);

    cudaFuncSetAttribute(gemm_h<0>, cudaFuncAttributeMaxDynamicSharedMemorySize, GEMM_SMEM);
    cudaFuncSetAttribute(gemm_h<1>, cudaFuncAttributeMaxDynamicSharedMemorySize, GEMM_SMEM);
    cudaFuncSetAttribute(gemm_h<2>, cudaFuncAttributeMaxDynamicSharedMemorySize, GEMM_SMEM);
    cudaFuncSetAttribute(attn_kernel, cudaFuncAttributeMaxDynamicSharedMemorySize, ATT_SMEM);

    embed_kernel<<<NTOK, 128>>>(track_ids, artist_ids, track_emb, artist_emb, pos_emb);

    for (int i = 0; i < LL; i++) {
        // --- QKV
        transpose_perm_h<<<dim3(DD/32, (3*DD)/32), dim3(32, 8)>>>(
            Wqkv + (size_t)i * DD * (3*DD), bqkv + (size_t)i * (3*DD), wt16);
        gemm_h<2><<<dim3((3*DD)/128, NTOK/128), 256, GEMM_SMEM>>>(
            x16, wt16, bp, qkv, 3*DD, DD);
        attn_kernel<<<dim3(BB*HH, 4), 256, ATT_SMEM>>>(qkv, track_ids, y);
        add_ln_kernel<<<NTOK/8, 256>>>(x, y, g1 + (size_t)i*DD, b1 + (size_t)i*DD, x, x16);
        // --- FF1
        transpose_h<<<dim3(DD/32, DFF/32), dim3(32, 8)>>>(
            Wff + (size_t)i * DD * DFF, wt16, DD, DFF);
        gemm_h<1><<<dim3(DFF/128, NTOK/128), 256, GEMM_SMEM>>>(
            x16, wt16, bff + (size_t)i * DFF, h16, DFF, DD);
        // --- FF2
        transpose_h<<<dim3(DFF/32, DD/32), dim3(32, 8)>>>(
            Wout + (size_t)i * DFF * DD, wt16, DFF, DD);
        gemm_h<0><<<dim3(DD/128, NTOK/128), 256, GEMM_SMEM>>>(
            h16, wt16, bout + (size_t)i * DD, y, DD, DFF);
        add_ln_kernel<<<NTOK/8, 256>>>(x, y, g2 + (size_t)i*DD, b2 + (size_t)i*DD,
                                       (i == LL-1) ? out : x, x16);
    }
}

// round 9
// speedup vs baseline: 5.4377x; 1.1078x over previous
#include <cuda_runtime.h>
#include <cuda_fp16.h>
#include <cstdint>

// ---------------------------------------------------------------------------
// Decoder: 6-layer transformer, B=32, T=512, D=512 (H=8, Dh=64), DFF=2048
// Round 8: fp16 flash attention (ldmatrix + k16 mma, P-in-register relayout),
//          all-weight fp16 conversion hoisted to 3 upfront launches.
//          (R7 plan; fixes __half2_as_uint -> pack_half2 PTX helper)
// ---------------------------------------------------------------------------

#define BB   32
#define TT   512
#define HH   8
#define DH   64
#define DD   512
#define DFF  2048
#define LL   6
#define NTOK (BB*TT)
#define PLANE ((size_t)NTOK * DD)

#define QKV_W  (3*DD*DD)          // 786432 halves per layer
#define FF_W   (DD*DFF)           // 1048576

__device__ float  g_x    [(size_t)NTOK * DD];
__device__ __half g_x16  [(size_t)NTOK * DD];
__device__ __half g_qkv16[(size_t)3 * PLANE];
__device__ float  g_y    [(size_t)NTOK * DD];
__device__ __half g_h16  [(size_t)NTOK * DFF];
__device__ float  g_bp   [LL * 3*DD];
__device__ __half g_wt16 [(size_t)LL * (QKV_W + 2*FF_W)];

__device__ __forceinline__ uint32_t smem_u32(const void* p) {
    uint32_t a;
    asm("{ .reg .u64 t; cvta.to.shared.u64 t, %1; cvt.u32.u64 %0, t; }" : "=r"(a) : "l"(p));
    return a;
}
__device__ __forceinline__ uint32_t pack_half2(float lo, float hi) {
    uint32_t r;
    asm("cvt.rn.f16x2.f32 %0, %1, %2;" : "=r"(r) : "f"(hi), "f"(lo));
    return r;
}
__device__ __forceinline__ void mma16h(float* c, const uint32_t* a, uint32_t b0, uint32_t b1) {
    asm volatile(
        "mma.sync.aligned.m16n8k16.row.col.f32.f16.f16.f32 "
        "{%0,%1,%2,%3}, {%4,%5,%6,%7}, {%8,%9}, {%0,%1,%2,%3};"
        : "+f"(c[0]), "+f"(c[1]), "+f"(c[2]), "+f"(c[3])
        : "r"(a[0]), "r"(a[1]), "r"(a[2]), "r"(a[3]), "r"(b0), "r"(b1));
}
__device__ __forceinline__ void ldm_x4(uint32_t* r, uint32_t addr) {
    asm volatile("ldmatrix.sync.aligned.m8n8.x4.shared.b16 {%0,%1,%2,%3}, [%4];"
                 : "=r"(r[0]), "=r"(r[1]), "=r"(r[2]), "=r"(r[3]) : "r"(addr));
}
__device__ __forceinline__ void ldm_x4_t(uint32_t* r, uint32_t addr) {
    asm volatile("ldmatrix.sync.aligned.m8n8.x4.trans.shared.b16 {%0,%1,%2,%3}, [%4];"
                 : "=r"(r[0]), "=r"(r[1]), "=r"(r[2]), "=r"(r[3]) : "r"(addr));
}
__device__ __forceinline__ void cp16(uint32_t dst, const void* src) {
    asm volatile("cp.async.cg.shared.global [%0], [%1], 16;" :: "r"(dst), "l"(src));
}
#define CP_COMMIT() asm volatile("cp.async.commit_group;" ::: "memory")
#define CP_WAIT(n)  asm volatile("cp.async.wait_group %0;" :: "n"(n) : "memory")

// ---------------------------------------------------------------------------
__global__ void embed_kernel(const int* __restrict__ tids, const int* __restrict__ aids,
                             const float* __restrict__ te, const float* __restrict__ ae,
                             const float* __restrict__ pe) {
    int token = blockIdx.x;
    int t = token & (TT - 1);
    int ti = tids[token], ai = aids[token];
    int d = threadIdx.x * 4;
    float4 t4 = *(const float4*)(te + (size_t)ti * DD + d);
    float4 a4 = *(const float4*)(ae + (size_t)ai * DD + d);
    float4 p4 = *(const float4*)(pe + (size_t)t  * DD + d);
    float4 o;
    o.x = 0.5f*(t4.x + a4.x) + p4.x;
    o.y = 0.5f*(t4.y + a4.y) + p4.y;
    o.z = 0.5f*(t4.z + a4.z) + p4.z;
    o.w = 0.5f*(t4.w + a4.w) + p4.w;
    *(float4*)(g_x + (size_t)token * DD + d) = o;
    __half2* x16 = (__half2*)(g_x16 + (size_t)token * DD + d);
    x16[0] = __floats2half2_rn(o.x, o.y);
    x16[1] = __floats2half2_rn(o.z, o.w);
}

// ---------------------------------------------------------------------------
// QKV weight: permute cols to planar + transpose to [N,K] + fp16. All layers
// via blockIdx.z. grid (DD/32, 3*DD/32, LL), block (32,8)
// ---------------------------------------------------------------------------
__global__ void transpose_perm_h(const float* __restrict__ Wq, const float* __restrict__ biasq) {
    __shared__ float t[32][33];
    int z = blockIdx.z;
    const float* W = Wq + (size_t)z * DD * (3*DD);
    const float* bias = biasq + (size_t)z * (3*DD);
    __half* Wt = g_wt16 + (size_t)z * QKV_W;
    int k0 = blockIdx.x * 32, n0 = blockIdx.y * 32;
    int tx = threadIdx.x, ty = threadIdx.y;
    int n = n0 + tx;
    int wh = n >> 9, rem = n & 511;
    int h = rem >> 6, dh = rem & 63;
    int o = h * 192 + dh * 3 + wh;
#pragma unroll
    for (int i = 0; i < 32; i += 8)
        t[ty + i][tx] = W[(size_t)(k0 + ty + i) * (3*DD) + o];
    if (blockIdx.x == 0 && ty == 0) g_bp[z * 3*DD + n] = bias[o];
    __syncthreads();
#pragma unroll
    for (int i = 0; i < 32; i += 8)
        Wt[(size_t)(n0 + ty + i) * DD + k0 + tx] = __float2half(t[tx][ty + i]);
}

// W [K,N] fp32 -> Wt16 [N,K] fp16, per-layer via blockIdx.z.
__global__ void transpose_h(const float* __restrict__ Wb, __half* __restrict__ Wtb,
                            int K, int N) {
    __shared__ float t[32][33];
    size_t wo = (size_t)blockIdx.z * K * N;
    const float* W = Wb + wo;
    __half* Wt = Wtb + wo;
    int k0 = blockIdx.x * 32, n0 = blockIdx.y * 32;
    int tx = threadIdx.x, ty = threadIdx.y;
#pragma unroll
    for (int i = 0; i < 32; i += 8)
        t[ty + i][tx] = W[(size_t)(k0 + ty + i) * N + n0 + tx];
    __syncthreads();
#pragma unroll
    for (int i = 0; i < 32; i += 8)
        Wt[(size_t)(n0 + ty + i) * K + k0 + tx] = __float2half(t[tx][ty + i]);
}

// ---------------------------------------------------------------------------
// fp16 GEMM: 128x128 tile, BK=64, 3-stage cp.async, ldmatrix frags.
// MODE: 0 fp32 out, 1 fp16 out + ReLU, 2 planar fp16 QKV out (Q scaled 1/8).
// ---------------------------------------------------------------------------
#define HROW 144
#define HSTAGE (256 * HROW)
#define NSTAGE 3
#define GEMM_SMEM (NSTAGE * HSTAGE)

template<int MODE>
__global__ __launch_bounds__(256, 2)
void gemm_h(const __half* __restrict__ A, const __half* __restrict__ Bt,
            const float* __restrict__ bias, void* __restrict__ Cout,
            int N, int K) {
    extern __shared__ char smc[];
    uint32_t sb = smem_u32(smc);

    int tid = threadIdx.x;
    int wid = tid >> 5, lane = tid & 31;
    int g = lane >> 2, tc = lane & 3;
    int wm0 = (wid & 3) * 32, wn0 = (wid >> 2) * 64;
    int m0 = blockIdx.y * 128, n0 = blockIdx.x * 128;

    int lrow = tid >> 1;
    int lch  = (tid & 1) * 4;
    const __half* Arow = A  + (size_t)(m0 + lrow) * K + lch * 8;
    const __half* Brow = Bt + (size_t)(n0 + lrow) * K + lch * 8;
    uint32_t dA0 = sb + lrow * HROW + lch * 16;
    uint32_t dB0 = dA0 + 128 * HROW;

    uint32_t aoff[2], boff[4];
#pragma unroll
    for (int mf = 0; mf < 2; mf++)
        aoff[mf] = (uint32_t)((wm0 + mf*16 + (lane & 15)) * HROW + ((lane >> 4) & 1) * 16);
#pragma unroll
    for (int q = 0; q < 4; q++)
        boff[q] = (uint32_t)((wn0 + q*16 + (lane & 7) + ((lane & 16) ? 8 : 0)) * HROW
                             + ((lane & 8) ? 16 : 0)) + 128 * HROW;

    float acc[2][8][4];
#pragma unroll
    for (int mf = 0; mf < 2; mf++)
#pragma unroll
        for (int nf = 0; nf < 8; nf++)
#pragma unroll
            for (int e = 0; e < 4; e++) acc[mf][nf][e] = 0.f;

    int nchunk = K >> 6;
#pragma unroll
    for (int s = 0; s < 2; s++) {
        uint32_t st = s * HSTAGE;
        const __half* An = Arow + (size_t)s * 64;
        const __half* Bn = Brow + (size_t)s * 64;
#pragma unroll
        for (int i = 0; i < 4; i++) {
            cp16(dA0 + st + i*16, An + i*8);
            cp16(dB0 + st + i*16, Bn + i*8);
        }
        CP_COMMIT();
    }

    for (int c = 0; c < nchunk; c++) {
        if (c + 2 <= nchunk) CP_WAIT(1); else CP_WAIT(0);
        __syncthreads();

        if (c + 2 < nchunk) {
            uint32_t st = (uint32_t)((c + 2) % NSTAGE) * HSTAGE;
            const __half* An = Arow + (size_t)(c + 2) * 64;
            const __half* Bn = Brow + (size_t)(c + 2) * 64;
#pragma unroll
            for (int i = 0; i < 4; i++) {
                cp16(dA0 + st + i*16, An + i*8);
                cp16(dB0 + st + i*16, Bn + i*8);
            }
            CP_COMMIT();
        }

        uint32_t stb = sb + (uint32_t)(c % NSTAGE) * HSTAGE;
#pragma unroll
        for (int ks = 0; ks < 4; ks++) {
            uint32_t koff = ks * 32;
            uint32_t a0[4], a1[4];
            ldm_x4(a0, stb + aoff[0] + koff);
            ldm_x4(a1, stb + aoff[1] + koff);
#pragma unroll
            for (int q = 0; q < 4; q++) {
                uint32_t bq[4];
                ldm_x4(bq, stb + boff[q] + koff);
                mma16h(acc[0][2*q],   a0, bq[0], bq[1]);
                mma16h(acc[1][2*q],   a1, bq[0], bq[1]);
                mma16h(acc[0][2*q+1], a0, bq[2], bq[3]);
                mma16h(acc[1][2*q+1], a1, bq[2], bq[3]);
            }
        }
    }

#pragma unroll
    for (int mf = 0; mf < 2; mf++) {
#pragma unroll
        for (int half = 0; half < 2; half++) {
            int row = m0 + wm0 + mf*16 + g + half*8;
#pragma unroll
            for (int nf = 0; nf < 8; nf++) {
                int col = n0 + wn0 + nf*8 + tc*2;
                float v0 = acc[mf][nf][half*2 + 0] + bias[col];
                float v1 = acc[mf][nf][half*2 + 1] + bias[col + 1];
                if (MODE == 1) {
                    v0 = fmaxf(v0, 0.f); v1 = fmaxf(v1, 0.f);
                    __half2* C = (__half2*)Cout;
                    C[((size_t)row * N + col) >> 1] = __floats2half2_rn(v0, v1);
                } else if (MODE == 2) {
                    int b = row >> 9, t = row & 511;
                    int wh = col >> 9, rem = col & 511;
                    int h = rem >> 6, dh = rem & 63;
                    if (wh == 0) { v0 *= 0.125f; v1 *= 0.125f; }
                    __half2* dst = (__half2*)((__half*)Cout + (size_t)wh * PLANE
                               + (((size_t)(b*HH + h)) * TT + t) * DH + dh);
                    *dst = __floats2half2_rn(v0, v1);
                } else {
                    *(float2*)((float*)Cout + (size_t)row * N + col) = make_float2(v0, v1);
                }
            }
        }
    }
}

// ---------------------------------------------------------------------------
// fp16 flash attention. Block = 128 q x one (b,h), 8 warps x 16 q.
// Key tiles 64; cp.async 3-stage K/V/pad; ldmatrix frags; m16n8k16 mma.
// P stays in registers (C-layout == A-layout for k16 fp16). Q pre-scaled.
// grid (B*H, 4), block 256.
// ---------------------------------------------------------------------------
#define A_STSZ 18688                 // K 9216 + V 9216 + pad 256
#define ATT_SMEM (18432 + 3 * A_STSZ)

__global__ __launch_bounds__(256, 2)
void attn_kernel(const __half* __restrict__ qkv, const int* __restrict__ track_ids,
                 float* __restrict__ y) {
    extern __shared__ char smc[];
    uint32_t sb = smem_u32(smc);

    int tid = threadIdx.x;
    int wid = tid >> 5, lane = tid & 31;
    int g = lane >> 2, tc = lane & 3;
    int bh = blockIdx.x;
    int b = bh >> 3, h = bh & 7;
    int q0 = blockIdx.y * 128;
    int wq0 = wid * 16;

    const __half* qpl = qkv;
    const __half* kpl = qkv + PLANE;
    const __half* vpl = qkv + 2 * PLANE;
    size_t hb = ((size_t)(b*HH + h)) * TT * DH;

    // ldmatrix per-lane offsets
    uint32_t aoffQ = (uint32_t)((wq0 + (lane & 15)) * HROW + ((lane >> 4) & 1) * 16);
    uint32_t boffK[4];
#pragma unroll
    for (int q = 0; q < 4; q++)
        boffK[q] = (uint32_t)((q*16 + (lane & 7) + ((lane & 16) ? 8 : 0)) * HROW
                              + ((lane & 8) ? 16 : 0));
    uint32_t voffV = (uint32_t)((lane & 15) * HROW + ((lane >> 4) << 4));

    // ---- issue Q + tile0 (group 0), tile1 (group 1) ----
#pragma unroll
    for (int it = 0; it < 4; it++) {
        int c = tid + it * 256;
        int row = c >> 3, sub = c & 7;
        cp16(sb + row * HROW + sub * 16, qpl + hb + (size_t)(q0 + row) * DH + sub * 8);
    }
#pragma unroll
    for (int s = 0; s < 2; s++) {
        uint32_t st = sb + 18432 + (uint32_t)s * A_STSZ;
#pragma unroll
        for (int it = 0; it < 2; it++) {
            int c = tid + it * 256;
            int row = c >> 3, sub = c & 7;
            cp16(st + row * HROW + sub * 16, kpl + hb + (size_t)(s*64 + row) * DH + sub * 8);
            cp16(st + 9216 + row * HROW + sub * 16, vpl + hb + (size_t)(s*64 + row) * DH + sub * 8);
        }
        if (tid < 16)
            cp16(st + 18432 + tid * 16, track_ids + b * TT + s*64 + tid * 4);
        CP_COMMIT();
    }

    float o_acc[8][4];
#pragma unroll
    for (int vf = 0; vf < 8; vf++)
#pragma unroll
        for (int e = 0; e < 4; e++) o_acc[vf][e] = 0.f;
    float m0r = -1e30f, m1r = -1e30f, l0r = 0.f, l1r = 0.f;

    int q_r0 = q0 + wq0 + g;
    int q_r1 = q_r0 + 8;
    int causal_tiles = (blockIdx.y + 1) * 2;

    for (int kt = 0; kt < TT/64; kt++) {
        if (kt >= causal_tiles) {
            if (__syncthreads_and(m0r > -5000.f && m1r > -5000.f)) break;
        }
        __syncthreads();   // WAR: stage (kt+2)%3 fully consumed (tile kt-1)
        if (kt + 2 < TT/64) {
            uint32_t st = sb + 18432 + (uint32_t)((kt + 2) % 3) * A_STSZ;
#pragma unroll
            for (int it = 0; it < 2; it++) {
                int c = tid + it * 256;
                int row = c >> 3, sub = c & 7;
                cp16(st + row * HROW + sub * 16, kpl + hb + (size_t)((kt+2)*64 + row) * DH + sub * 8);
                cp16(st + 9216 + row * HROW + sub * 16, vpl + hb + (size_t)((kt+2)*64 + row) * DH + sub * 8);
            }
            if (tid < 16)
                cp16(st + 18432 + tid * 16, track_ids + b * TT + (kt+2)*64 + tid * 4);
            CP_COMMIT();
            CP_WAIT(2);
        } else if (kt + 1 < TT/64) {
            CP_WAIT(1);
        } else {
            CP_WAIT(0);
        }
        __syncthreads();   // RAW: tile kt visible to all

        bool need = (kt*64 <= q0 + wq0 + 15)
                  || __any_sync(0xffffffffu, m0r <= -5000.f || m1r <= -5000.f);
        if (!need) continue;

        uint32_t stK = sb + 18432 + (uint32_t)(kt % 3) * A_STSZ;
        uint32_t stV = stK + 9216;
        const int* padp = (const int*)(smc + 18432 + (size_t)(kt % 3) * A_STSZ + 18432);

        // ---- S = Q @ K^T ----
        float sacc[8][4];
#pragma unroll
        for (int nf = 0; nf < 8; nf++)
#pragma unroll
            for (int e = 0; e < 4; e++) sacc[nf][e] = 0.f;
#pragma unroll
        for (int ks = 0; ks < 4; ks++) {
            uint32_t koff = ks * 32;
            uint32_t aq[4];
            ldm_x4(aq, sb + aoffQ + koff);
#pragma unroll
            for (int q = 0; q < 4; q++) {
                uint32_t bk[4];
                ldm_x4(bk, stK + boffK[q] + koff);
                mma16h(sacc[2*q],   aq, bk[0], bk[1]);
                mma16h(sacc[2*q+1], aq, bk[2], bk[3]);
            }
        }

        // ---- mask + online softmax ----
        float tmax0 = -1e30f, tmax1 = -1e30f;
#pragma unroll
        for (int nf = 0; nf < 8; nf++) {
            int kcol = kt*64 + nf*8 + tc*2;
#pragma unroll
            for (int e = 0; e < 2; e++) {
                int key = kcol + e;
                bool pad = (padp[key - kt*64] != 0);
                float s0 = sacc[nf][e]   + ((key <= q_r0 && pad) ? 0.f : -10000.f);
                float s1 = sacc[nf][e+2] + ((key <= q_r1 && pad) ? 0.f : -10000.f);
                sacc[nf][e] = s0; sacc[nf][e+2] = s1;
                tmax0 = fmaxf(tmax0, s0);
                tmax1 = fmaxf(tmax1, s1);
            }
        }
        tmax0 = fmaxf(tmax0, __shfl_xor_sync(0xffffffffu, tmax0, 1));
        tmax0 = fmaxf(tmax0, __shfl_xor_sync(0xffffffffu, tmax0, 2));
        tmax1 = fmaxf(tmax1, __shfl_xor_sync(0xffffffffu, tmax1, 1));
        tmax1 = fmaxf(tmax1, __shfl_xor_sync(0xffffffffu, tmax1, 2));

        float mn0 = fmaxf(m0r, tmax0), mn1 = fmaxf(m1r, tmax1);
        float c0 = __expf(m0r - mn0),  c1 = __expf(m1r - mn1);
        m0r = mn0; m1r = mn1;

        float ls0 = 0.f, ls1 = 0.f;
#pragma unroll
        for (int nf = 0; nf < 8; nf++) {
#pragma unroll
            for (int e = 0; e < 2; e++) {
                float p0 = __expf(sacc[nf][e]   - mn0);
                float p1 = __expf(sacc[nf][e+2] - mn1);
                ls0 += p0; ls1 += p1;
                sacc[nf][e] = p0; sacc[nf][e+2] = p1;
            }
        }
        ls0 += __shfl_xor_sync(0xffffffffu, ls0, 1);
        ls0 += __shfl_xor_sync(0xffffffffu, ls0, 2);
        ls1 += __shfl_xor_sync(0xffffffffu, ls1, 1);
        ls1 += __shfl_xor_sync(0xffffffffu, ls1, 2);
        l0r = l0r * c0 + ls0;
        l1r = l1r * c1 + ls1;

#pragma unroll
        for (int vf = 0; vf < 8; vf++) {
            o_acc[vf][0] *= c0; o_acc[vf][1] *= c0;
            o_acc[vf][2] *= c1; o_acc[vf][3] *= c1;
        }

        // ---- O += P @ V : P C-layout == A-layout (fp16 k16), V^T via ldm.trans
#pragma unroll
        for (int ks = 0; ks < 4; ks++) {
            uint32_t a[4];
            a[0] = pack_half2(sacc[2*ks][0],   sacc[2*ks][1]);
            a[1] = pack_half2(sacc[2*ks][2],   sacc[2*ks][3]);
            a[2] = pack_half2(sacc[2*ks+1][0], sacc[2*ks+1][1]);
            a[3] = pack_half2(sacc[2*ks+1][2], sacc[2*ks+1][3]);
#pragma unroll
            for (int j = 0; j < 4; j++) {
                uint32_t bv[4];
                ldm_x4_t(bv, stV + (uint32_t)(ks * 16 * HROW) + j*32 + voffV);
                mma16h(o_acc[2*j],   a, bv[0], bv[1]);
                mma16h(o_acc[2*j+1], a, bv[2], bv[3]);
            }
        }
    }

    float inv0 = 1.f / l0r, inv1 = 1.f / l1r;
    float* y0 = y + (size_t)(b * TT + q_r0) * DD + h * DH;
    float* y1 = y + (size_t)(b * TT + q_r1) * DD + h * DH;
#pragma unroll
    for (int vf = 0; vf < 8; vf++) {
        int dh = vf*8 + tc*2;
        *(float2*)(y0 + dh) = make_float2(o_acc[vf][0] * inv0, o_acc[vf][1] * inv0);
        *(float2*)(y1 + dh) = make_float2(o_acc[vf][2] * inv1, o_acc[vf][3] * inv1);
    }
}

// ---------------------------------------------------------------------------
__global__ void add_ln_kernel(const float* __restrict__ x, const float* __restrict__ y,
                              const float* __restrict__ g, const float* __restrict__ b,
                              float* __restrict__ out, __half* __restrict__ out16) {
    int token = blockIdx.x * 8 + (threadIdx.x >> 5);
    int lane = threadIdx.x & 31;
    const float4* xr = (const float4*)(x + (size_t)token * DD);
    const float4* yr = (const float4*)(y + (size_t)token * DD);

    float4 v[4];
    float s = 0.f;
#pragma unroll
    for (int c = 0; c < 4; c++) {
        float4 a = xr[lane + 32*c];
        float4 w = yr[lane + 32*c];
        v[c].x = a.x + w.x; v[c].y = a.y + w.y;
        v[c].z = a.z + w.z; v[c].w = a.w + w.w;
        s += v[c].x + v[c].y + v[c].z + v[c].w;
    }
#pragma unroll
    for (int off = 16; off; off >>= 1) s += __shfl_xor_sync(0xffffffffu, s, off);
    float mu = s * (1.f / 512.f);

    float sq = 0.f;
#pragma unroll
    for (int c = 0; c < 4; c++) {
        float dx = v[c].x - mu, dy = v[c].y - mu, dz = v[c].z - mu, dw = v[c].w - mu;
        sq += dx*dx + dy*dy + dz*dz + dw*dw;
    }
#pragma unroll
    for (int off = 16; off; off >>= 1) sq += __shfl_xor_sync(0xffffffffu, sq, off);
    float r = rsqrtf(sq * (1.f / 512.f) + 1e-5f);

    const float4* g4 = (const float4*)g;
    const float4* b4 = (const float4*)b;
    float4* orow = (float4*)(out + (size_t)token * DD);
    __half2* o16 = (__half2*)(out16 + (size_t)token * DD);
#pragma unroll
    for (int c = 0; c < 4; c++) {
        int idx = lane + 32*c;
        float4 gg = g4[idx], bb = b4[idx];
        float4 o;
        o.x = (v[c].x - mu) * r * gg.x + bb.x;
        o.y = (v[c].y - mu) * r * gg.y + bb.y;
        o.z = (v[c].z - mu) * r * gg.z + bb.z;
        o.w = (v[c].w - mu) * r * gg.w + bb.w;
        orow[idx] = o;
        o16[idx*2 + 0] = __floats2half2_rn(o.x, o.y);
        o16[idx*2 + 1] = __floats2half2_rn(o.z, o.w);
    }
}

// ---------------------------------------------------------------------------
extern "C" void kernel_launch(void* const* d_in, const int* in_sizes, int n_in,
                              void* d_out, int out_size) {
    const int*   track_ids  = (const int*)  d_in[0];
    const int*   artist_ids = (const int*)  d_in[1];
    const float* track_emb  = (const float*)d_in[2];
    const float* artist_emb = (const float*)d_in[3];
    const float* pos_emb    = (const float*)d_in[4];
    const float* Wqkv       = (const float*)d_in[5];
    const float* bqkv       = (const float*)d_in[6];
    const float* Wff        = (const float*)d_in[7];
    const float* bff        = (const float*)d_in[8];
    const float* Wout       = (const float*)d_in[9];
    const float* bout       = (const float*)d_in[10];
    const float* g1         = (const float*)d_in[11];
    const float* b1         = (const float*)d_in[12];
    const float* g2         = (const float*)d_in[13];
    const float* b2         = (const float*)d_in[14];
    float* out = (float*)d_out;

    float *x, *y, *bp;
    __half *x16, *h16, *wt16, *qkv16;
    cudaGetSymbolAddress((void**)&x,     g_x);
    cudaGetSymbolAddress((void**)&x16,   g_x16);
    cudaGetSymbolAddress((void**)&qkv16, g_qkv16);
    cudaGetSymbolAddress((void**)&y,     g_y);
    cudaGetSymbolAddress((void**)&h16,   g_h16);
    cudaGetSymbolAddress((void**)&bp,    g_bp);
    cudaGetSymbolAddress((void**)&wt16,  g_wt16);

    __half* wqkv16 = wt16;
    __half* wff16  = wt16 + (size_t)LL * QKV_W;
    __half* wout16 = wff16 + (size_t)LL * FF_W;

    cudaFuncSetAttribute(gemm_h<0>, cudaFuncAttributeMaxDynamicSharedMemorySize, GEMM_SMEM);
    cudaFuncSetAttribute(gemm_h<1>, cudaFuncAttributeMaxDynamicSharedMemorySize, GEMM_SMEM);
    cudaFuncSetAttribute(gemm_h<2>, cudaFuncAttributeMaxDynamicSharedMemorySize, GEMM_SMEM);
    cudaFuncSetAttribute(attn_kernel, cudaFuncAttributeMaxDynamicSharedMemorySize, ATT_SMEM);

    // one-time weight conversion (3 launches, all layers)
    transpose_perm_h<<<dim3(DD/32, (3*DD)/32, LL), dim3(32, 8)>>>(Wqkv, bqkv);
    transpose_h<<<dim3(DD/32, DFF/32, LL), dim3(32, 8)>>>(Wff, wff16, DD, DFF);
    transpose_h<<<dim3(DFF/32, DD/32, LL), dim3(32, 8)>>>(Wout, wout16, DFF, DD);

    embed_kernel<<<NTOK, 128>>>(track_ids, artist_ids, track_emb, artist_emb, pos_emb);

    for (int i = 0; i < LL; i++) {
        gemm_h<2><<<dim3((3*DD)/128, NTOK/128), 256, GEMM_SMEM>>>(
            x16, wqkv16 + (size_t)i * QKV_W, bp + (size_t)i * 3*DD, qkv16, 3*DD, DD);
        attn_kernel<<<dim3(BB*HH, 4), 256, ATT_SMEM>>>(qkv16, track_ids, y);
        add_ln_kernel<<<NTOK/8, 256>>>(x, y, g1 + (size_t)i*DD, b1 + (size_t)i*DD, x, x16);
        gemm_h<1><<<dim3(DFF/128, NTOK/128), 256, GEMM_SMEM>>>(
            x16, wff16 + (size_t)i * FF_W, bff + (size_t)i * DFF, h16, DFF, DD);
        gemm_h<0><<<dim3(DD/128, NTOK/128), 256, GEMM_SMEM>>>(
            h16, wout16 + (size_t)i * FF_W, bout + (size_t)i * DD, y, DD, DFF);
        add_ln_kernel<<<NTOK/8, 256>>>(x, y, g2 + (size_t)i*DD, b2 + (size_t)i*DD,
                                       (i == LL-1) ? out : x, x16);
    }
}

// round 10
// speedup vs baseline: 6.6840x; 1.2292x over previous
#include <cuda_runtime.h>
#include <cuda_fp16.h>
#include <cstdint>

// ---------------------------------------------------------------------------
// Decoder: 6-layer transformer, B=32, T=512, D=512 (H=8, Dh=64), DFF=2048
// Round 9: GEMM re-tiled to 256x128 CTA / 64x64 warp (8 LDSM : 32 HMMA),
//          3-stage cp.async; fp16 flash attention unchanged.
// ---------------------------------------------------------------------------

#define BB   32
#define TT   512
#define HH   8
#define DH   64
#define DD   512
#define DFF  2048
#define LL   6
#define NTOK (BB*TT)
#define PLANE ((size_t)NTOK * DD)

#define QKV_W  (3*DD*DD)
#define FF_W   (DD*DFF)

__device__ float  g_x    [(size_t)NTOK * DD];
__device__ __half g_x16  [(size_t)NTOK * DD];
__device__ __half g_qkv16[(size_t)3 * PLANE];
__device__ float  g_y    [(size_t)NTOK * DD];
__device__ __half g_h16  [(size_t)NTOK * DFF];
__device__ float  g_bp   [LL * 3*DD];
__device__ __half g_wt16 [(size_t)LL * (QKV_W + 2*FF_W)];

__device__ __forceinline__ uint32_t smem_u32(const void* p) {
    uint32_t a;
    asm("{ .reg .u64 t; cvta.to.shared.u64 t, %1; cvt.u32.u64 %0, t; }" : "=r"(a) : "l"(p));
    return a;
}
__device__ __forceinline__ uint32_t pack_half2(float lo, float hi) {
    uint32_t r;
    asm("cvt.rn.f16x2.f32 %0, %1, %2;" : "=r"(r) : "f"(hi), "f"(lo));
    return r;
}
__device__ __forceinline__ void mma16h(float* c, const uint32_t* a, uint32_t b0, uint32_t b1) {
    asm volatile(
        "mma.sync.aligned.m16n8k16.row.col.f32.f16.f16.f32 "
        "{%0,%1,%2,%3}, {%4,%5,%6,%7}, {%8,%9}, {%0,%1,%2,%3};"
        : "+f"(c[0]), "+f"(c[1]), "+f"(c[2]), "+f"(c[3])
        : "r"(a[0]), "r"(a[1]), "r"(a[2]), "r"(a[3]), "r"(b0), "r"(b1));
}
__device__ __forceinline__ void ldm_x4(uint32_t* r, uint32_t addr) {
    asm volatile("ldmatrix.sync.aligned.m8n8.x4.shared.b16 {%0,%1,%2,%3}, [%4];"
                 : "=r"(r[0]), "=r"(r[1]), "=r"(r[2]), "=r"(r[3]) : "r"(addr));
}
__device__ __forceinline__ void ldm_x4_t(uint32_t* r, uint32_t addr) {
    asm volatile("ldmatrix.sync.aligned.m8n8.x4.trans.shared.b16 {%0,%1,%2,%3}, [%4];"
                 : "=r"(r[0]), "=r"(r[1]), "=r"(r[2]), "=r"(r[3]) : "r"(addr));
}
__device__ __forceinline__ void cp16(uint32_t dst, const void* src) {
    asm volatile("cp.async.cg.shared.global [%0], [%1], 16;" :: "r"(dst), "l"(src));
}
#define CP_COMMIT() asm volatile("cp.async.commit_group;" ::: "memory")
#define CP_WAIT(n)  asm volatile("cp.async.wait_group %0;" :: "n"(n) : "memory")

// ---------------------------------------------------------------------------
__global__ void embed_kernel(const int* __restrict__ tids, const int* __restrict__ aids,
                             const float* __restrict__ te, const float* __restrict__ ae,
                             const float* __restrict__ pe) {
    int token = blockIdx.x;
    int t = token & (TT - 1);
    int ti = tids[token], ai = aids[token];
    int d = threadIdx.x * 4;
    float4 t4 = *(const float4*)(te + (size_t)ti * DD + d);
    float4 a4 = *(const float4*)(ae + (size_t)ai * DD + d);
    float4 p4 = *(const float4*)(pe + (size_t)t  * DD + d);
    float4 o;
    o.x = 0.5f*(t4.x + a4.x) + p4.x;
    o.y = 0.5f*(t4.y + a4.y) + p4.y;
    o.z = 0.5f*(t4.z + a4.z) + p4.z;
    o.w = 0.5f*(t4.w + a4.w) + p4.w;
    *(float4*)(g_x + (size_t)token * DD + d) = o;
    __half2* x16 = (__half2*)(g_x16 + (size_t)token * DD + d);
    x16[0] = __floats2half2_rn(o.x, o.y);
    x16[1] = __floats2half2_rn(o.z, o.w);
}

// ---------------------------------------------------------------------------
__global__ void transpose_perm_h(const float* __restrict__ Wq, const float* __restrict__ biasq) {
    __shared__ float t[32][33];
    int z = blockIdx.z;
    const float* W = Wq + (size_t)z * DD * (3*DD);
    const float* bias = biasq + (size_t)z * (3*DD);
    __half* Wt = g_wt16 + (size_t)z * QKV_W;
    int k0 = blockIdx.x * 32, n0 = blockIdx.y * 32;
    int tx = threadIdx.x, ty = threadIdx.y;
    int n = n0 + tx;
    int wh = n >> 9, rem = n & 511;
    int h = rem >> 6, dh = rem & 63;
    int o = h * 192 + dh * 3 + wh;
#pragma unroll
    for (int i = 0; i < 32; i += 8)
        t[ty + i][tx] = W[(size_t)(k0 + ty + i) * (3*DD) + o];
    if (blockIdx.x == 0 && ty == 0) g_bp[z * 3*DD + n] = bias[o];
    __syncthreads();
#pragma unroll
    for (int i = 0; i < 32; i += 8)
        Wt[(size_t)(n0 + ty + i) * DD + k0 + tx] = __float2half(t[tx][ty + i]);
}

__global__ void transpose_h(const float* __restrict__ Wb, __half* __restrict__ Wtb,
                            int K, int N) {
    __shared__ float t[32][33];
    size_t wo = (size_t)blockIdx.z * K * N;
    const float* W = Wb + wo;
    __half* Wt = Wtb + wo;
    int k0 = blockIdx.x * 32, n0 = blockIdx.y * 32;
    int tx = threadIdx.x, ty = threadIdx.y;
#pragma unroll
    for (int i = 0; i < 32; i += 8)
        t[ty + i][tx] = W[(size_t)(k0 + ty + i) * N + n0 + tx];
    __syncthreads();
#pragma unroll
    for (int i = 0; i < 32; i += 8)
        Wt[(size_t)(n0 + ty + i) * K + k0 + tx] = __float2half(t[tx][ty + i]);
}

// ---------------------------------------------------------------------------
// fp16 GEMM: C[M,N] = A16[M,K] @ Bt16[N,K]^T + bias.
// CTA tile 256x128, warp tile 64x64 (8 warps: 4 in M x 2 in N), BK=64,
// 3-stage cp.async, ldmatrix frags. Per k-step: 8 LDSM : 32 HMMA.
// MODE: 0 fp32 out, 1 fp16 out + ReLU, 2 planar fp16 QKV out (Q scaled 1/8).
// ---------------------------------------------------------------------------
#define HROW 144
#define HSTAGE ((256 + 128) * HROW)     // A 256 rows + B 128 rows
#define B_OFF  (256 * HROW)
#define NSTAGE 3
#define GEMM_SMEM (NSTAGE * HSTAGE)

template<int MODE>
__global__ __launch_bounds__(256, 1)
void gemm_h(const __half* __restrict__ A, const __half* __restrict__ Bt,
            const float* __restrict__ bias, void* __restrict__ Cout,
            int N, int K) {
    extern __shared__ char smc[];
    uint32_t sb = smem_u32(smc);

    int tid = threadIdx.x;
    int wid = tid >> 5, lane = tid & 31;
    int g = lane >> 2, tc = lane & 3;
    int wm0 = (wid & 3) * 64, wn0 = (wid >> 2) * 64;
    int m0 = blockIdx.y * 256, n0 = blockIdx.x * 128;

    // cp.async loader mapping: 256 threads; thread -> (row lr+32*it, 16B chunk sub)
    int lr  = tid >> 3;          // 0..31
    int sub = tid & 7;           // 0..7 (16B chunk within 128B row)
    const __half* Abase = A  + (size_t)(m0 + lr) * K + sub * 8;
    const __half* Bbase = Bt + (size_t)(n0 + lr) * K + sub * 8;
    uint32_t dA0 = sb + lr * HROW + sub * 16;
    uint32_t dB0 = sb + B_OFF + lr * HROW + sub * 16;

    // ldmatrix per-lane offsets
    uint32_t aoff[4], boff[4];
#pragma unroll
    for (int mf = 0; mf < 4; mf++)
        aoff[mf] = (uint32_t)((wm0 + mf*16 + (lane & 15)) * HROW + ((lane >> 4) & 1) * 16);
#pragma unroll
    for (int q = 0; q < 4; q++)
        boff[q] = (uint32_t)((wn0 + q*16 + (lane & 7) + ((lane & 16) ? 8 : 0)) * HROW
                             + ((lane & 8) ? 16 : 0)) + B_OFF;

    float acc[4][8][4];
#pragma unroll
    for (int mf = 0; mf < 4; mf++)
#pragma unroll
        for (int nf = 0; nf < 8; nf++)
#pragma unroll
            for (int e = 0; e < 4; e++) acc[mf][nf][e] = 0.f;

    int nchunk = K >> 6;

    // prologue: stages 0 and 1
#pragma unroll
    for (int s = 0; s < 2; s++) {
        uint32_t st = s * HSTAGE;
        const __half* An = Abase + (size_t)s * 64;
        const __half* Bn = Bbase + (size_t)s * 64;
#pragma unroll
        for (int it = 0; it < 8; it++)
            cp16(dA0 + st + it * 32 * HROW, An + (size_t)(32 * it) * K);
#pragma unroll
        for (int it = 0; it < 4; it++)
            cp16(dB0 + st + it * 32 * HROW, Bn + (size_t)(32 * it) * K);
        CP_COMMIT();
    }

    for (int c = 0; c < nchunk; c++) {
        if (c + 2 <= nchunk) CP_WAIT(1); else CP_WAIT(0);
        __syncthreads();

        if (c + 2 < nchunk) {
            uint32_t st = (uint32_t)((c + 2) % NSTAGE) * HSTAGE;
            const __half* An = Abase + (size_t)(c + 2) * 64;
            const __half* Bn = Bbase + (size_t)(c + 2) * 64;
#pragma unroll
            for (int it = 0; it < 8; it++)
                cp16(dA0 + st + it * 32 * HROW, An + (size_t)(32 * it) * K);
#pragma unroll
            for (int it = 0; it < 4; it++)
                cp16(dB0 + st + it * 32 * HROW, Bn + (size_t)(32 * it) * K);
            CP_COMMIT();
        }

        uint32_t stb = sb + (uint32_t)(c % NSTAGE) * HSTAGE;
#pragma unroll
        for (int ks = 0; ks < 4; ks++) {
            uint32_t koff = ks * 32;
            uint32_t a[4][4];
#pragma unroll
            for (int mf = 0; mf < 4; mf++)
                ldm_x4(a[mf], stb + aoff[mf] + koff);
#pragma unroll
            for (int q = 0; q < 4; q++) {
                uint32_t bq[4];
                ldm_x4(bq, stb + boff[q] + koff);
#pragma unroll
                for (int mf = 0; mf < 4; mf++) {
                    mma16h(acc[mf][2*q],   a[mf], bq[0], bq[1]);
                    mma16h(acc[mf][2*q+1], a[mf], bq[2], bq[3]);
                }
            }
        }
    }

    // ---- epilogue ----
#pragma unroll
    for (int mf = 0; mf < 4; mf++) {
#pragma unroll
        for (int half = 0; half < 2; half++) {
            int row = m0 + wm0 + mf*16 + g + half*8;
#pragma unroll
            for (int nf = 0; nf < 8; nf++) {
                int col = n0 + wn0 + nf*8 + tc*2;
                float v0 = acc[mf][nf][half*2 + 0] + bias[col];
                float v1 = acc[mf][nf][half*2 + 1] + bias[col + 1];
                if (MODE == 1) {
                    v0 = fmaxf(v0, 0.f); v1 = fmaxf(v1, 0.f);
                    __half2* C = (__half2*)Cout;
                    C[((size_t)row * N + col) >> 1] = __floats2half2_rn(v0, v1);
                } else if (MODE == 2) {
                    int b = row >> 9, t = row & 511;
                    int wh = col >> 9, rem = col & 511;
                    int h = rem >> 6, dh = rem & 63;
                    if (wh == 0) { v0 *= 0.125f; v1 *= 0.125f; }
                    __half2* dst = (__half2*)((__half*)Cout + (size_t)wh * PLANE
                               + (((size_t)(b*HH + h)) * TT + t) * DH + dh);
                    *dst = __floats2half2_rn(v0, v1);
                } else {
                    *(float2*)((float*)Cout + (size_t)row * N + col) = make_float2(v0, v1);
                }
            }
        }
    }
}

// ---------------------------------------------------------------------------
// fp16 flash attention (round 8, unchanged)
// ---------------------------------------------------------------------------
#define A_STSZ 18688                 // K 9216 + V 9216 + pad 256
#define ATT_SMEM (18432 + 3 * A_STSZ)

__global__ __launch_bounds__(256, 2)
void attn_kernel(const __half* __restrict__ qkv, const int* __restrict__ track_ids,
                 float* __restrict__ y) {
    extern __shared__ char smc[];
    uint32_t sb = smem_u32(smc);

    int tid = threadIdx.x;
    int wid = tid >> 5, lane = tid & 31;
    int g = lane >> 2, tc = lane & 3;
    int bh = blockIdx.x;
    int b = bh >> 3, h = bh & 7;
    int q0 = blockIdx.y * 128;
    int wq0 = wid * 16;

    const __half* qpl = qkv;
    const __half* kpl = qkv + PLANE;
    const __half* vpl = qkv + 2 * PLANE;
    size_t hb = ((size_t)(b*HH + h)) * TT * DH;

    uint32_t aoffQ = (uint32_t)((wq0 + (lane & 15)) * HROW + ((lane >> 4) & 1) * 16);
    uint32_t boffK[4];
#pragma unroll
    for (int q = 0; q < 4; q++)
        boffK[q] = (uint32_t)((q*16 + (lane & 7) + ((lane & 16) ? 8 : 0)) * HROW
                              + ((lane & 8) ? 16 : 0));
    uint32_t voffV = (uint32_t)((lane & 15) * HROW + ((lane >> 4) << 4));

#pragma unroll
    for (int it = 0; it < 4; it++) {
        int c = tid + it * 256;
        int row = c >> 3, sub = c & 7;
        cp16(sb + row * HROW + sub * 16, qpl + hb + (size_t)(q0 + row) * DH + sub * 8);
    }
#pragma unroll
    for (int s = 0; s < 2; s++) {
        uint32_t st = sb + 18432 + (uint32_t)s * A_STSZ;
#pragma unroll
        for (int it = 0; it < 2; it++) {
            int c = tid + it * 256;
            int row = c >> 3, sub = c & 7;
            cp16(st + row * HROW + sub * 16, kpl + hb + (size_t)(s*64 + row) * DH + sub * 8);
            cp16(st + 9216 + row * HROW + sub * 16, vpl + hb + (size_t)(s*64 + row) * DH + sub * 8);
        }
        if (tid < 16)
            cp16(st + 18432 + tid * 16, track_ids + b * TT + s*64 + tid * 4);
        CP_COMMIT();
    }

    float o_acc[8][4];
#pragma unroll
    for (int vf = 0; vf < 8; vf++)
#pragma unroll
        for (int e = 0; e < 4; e++) o_acc[vf][e] = 0.f;
    float m0r = -1e30f, m1r = -1e30f, l0r = 0.f, l1r = 0.f;

    int q_r0 = q0 + wq0 + g;
    int q_r1 = q_r0 + 8;
    int causal_tiles = (blockIdx.y + 1) * 2;

    for (int kt = 0; kt < TT/64; kt++) {
        if (kt >= causal_tiles) {
            if (__syncthreads_and(m0r > -5000.f && m1r > -5000.f)) break;
        }
        __syncthreads();
        if (kt + 2 < TT/64) {
            uint32_t st = sb + 18432 + (uint32_t)((kt + 2) % 3) * A_STSZ;
#pragma unroll
            for (int it = 0; it < 2; it++) {
                int c = tid + it * 256;
                int row = c >> 3, sub = c & 7;
                cp16(st + row * HROW + sub * 16, kpl + hb + (size_t)((kt+2)*64 + row) * DH + sub * 8);
                cp16(st + 9216 + row * HROW + sub * 16, vpl + hb + (size_t)((kt+2)*64 + row) * DH + sub * 8);
            }
            if (tid < 16)
                cp16(st + 18432 + tid * 16, track_ids + b * TT + (kt+2)*64 + tid * 4);
            CP_COMMIT();
            CP_WAIT(2);
        } else if (kt + 1 < TT/64) {
            CP_WAIT(1);
        } else {
            CP_WAIT(0);
        }
        __syncthreads();

        bool need = (kt*64 <= q0 + wq0 + 15)
                  || __any_sync(0xffffffffu, m0r <= -5000.f || m1r <= -5000.f);
        if (!need) continue;

        uint32_t stK = sb + 18432 + (uint32_t)(kt % 3) * A_STSZ;
        uint32_t stV = stK + 9216;
        const int* padp = (const int*)(smc + 18432 + (size_t)(kt % 3) * A_STSZ + 18432);

        float sacc[8][4];
#pragma unroll
        for (int nf = 0; nf < 8; nf++)
#pragma unroll
            for (int e = 0; e < 4; e++) sacc[nf][e] = 0.f;
#pragma unroll
        for (int ks = 0; ks < 4; ks++) {
            uint32_t koff = ks * 32;
            uint32_t aq[4];
            ldm_x4(aq, sb + aoffQ + koff);
#pragma unroll
            for (int q = 0; q < 4; q++) {
                uint32_t bk[4];
                ldm_x4(bk, stK + boffK[q] + koff);
                mma16h(sacc[2*q],   aq, bk[0], bk[1]);
                mma16h(sacc[2*q+1], aq, bk[2], bk[3]);
            }
        }

        float tmax0 = -1e30f, tmax1 = -1e30f;
#pragma unroll
        for (int nf = 0; nf < 8; nf++) {
            int kcol = kt*64 + nf*8 + tc*2;
#pragma unroll
            for (int e = 0; e < 2; e++) {
                int key = kcol + e;
                bool pad = (padp[key - kt*64] != 0);
                float s0 = sacc[nf][e]   + ((key <= q_r0 && pad) ? 0.f : -10000.f);
                float s1 = sacc[nf][e+2] + ((key <= q_r1 && pad) ? 0.f : -10000.f);
                sacc[nf][e] = s0; sacc[nf][e+2] = s1;
                tmax0 = fmaxf(tmax0, s0);
                tmax1 = fmaxf(tmax1, s1);
            }
        }
        tmax0 = fmaxf(tmax0, __shfl_xor_sync(0xffffffffu, tmax0, 1));
        tmax0 = fmaxf(tmax0, __shfl_xor_sync(0xffffffffu, tmax0, 2));
        tmax1 = fmaxf(tmax1, __shfl_xor_sync(0xffffffffu, tmax1, 1));
        tmax1 = fmaxf(tmax1, __shfl_xor_sync(0xffffffffu, tmax1, 2));

        float mn0 = fmaxf(m0r, tmax0), mn1 = fmaxf(m1r, tmax1);
        float c0 = __expf(m0r - mn0),  c1 = __expf(m1r - mn1);
        m0r = mn0; m1r = mn1;

        float ls0 = 0.f, ls1 = 0.f;
#pragma unroll
        for (int nf = 0; nf < 8; nf++) {
#pragma unroll
            for (int e = 0; e < 2; e++) {
                float p0 = __expf(sacc[nf][e]   - mn0);
                float p1 = __expf(sacc[nf][e+2] - mn1);
                ls0 += p0; ls1 += p1;
                sacc[nf][e] = p0; sacc[nf][e+2] = p1;
            }
        }
        ls0 += __shfl_xor_sync(0xffffffffu, ls0, 1);
        ls0 += __shfl_xor_sync(0xffffffffu, ls0, 2);
        ls1 += __shfl_xor_sync(0xffffffffu, ls1, 1);
        ls1 += __shfl_xor_sync(0xffffffffu, ls1, 2);
        l0r = l0r * c0 + ls0;
        l1r = l1r * c1 + ls1;

#pragma unroll
        for (int vf = 0; vf < 8; vf++) {
            o_acc[vf][0] *= c0; o_acc[vf][1] *= c0;
            o_acc[vf][2] *= c1; o_acc[vf][3] *= c1;
        }

#pragma unroll
        for (int ks = 0; ks < 4; ks++) {
            uint32_t a[4];
            a[0] = pack_half2(sacc[2*ks][0],   sacc[2*ks][1]);
            a[1] = pack_half2(sacc[2*ks][2],   sacc[2*ks][3]);
            a[2] = pack_half2(sacc[2*ks+1][0], sacc[2*ks+1][1]);
            a[3] = pack_half2(sacc[2*ks+1][2], sacc[2*ks+1][3]);
#pragma unroll
            for (int j = 0; j < 4; j++) {
                uint32_t bv[4];
                ldm_x4_t(bv, stV + (uint32_t)(ks * 16 * HROW) + j*32 + voffV);
                mma16h(o_acc[2*j],   a, bv[0], bv[1]);
                mma16h(o_acc[2*j+1], a, bv[2], bv[3]);
            }
        }
    }

    float inv0 = 1.f / l0r, inv1 = 1.f / l1r;
    float* y0 = y + (size_t)(b * TT + q_r0) * DD + h * DH;
    float* y1 = y + (size_t)(b * TT + q_r1) * DD + h * DH;
#pragma unroll
    for (int vf = 0; vf < 8; vf++) {
        int dh = vf*8 + tc*2;
        *(float2*)(y0 + dh) = make_float2(o_acc[vf][0] * inv0, o_acc[vf][1] * inv0);
        *(float2*)(y1 + dh) = make_float2(o_acc[vf][2] * inv1, o_acc[vf][3] * inv1);
    }
}

// ---------------------------------------------------------------------------
__global__ void add_ln_kernel(const float* __restrict__ x, const float* __restrict__ y,
                              const float* __restrict__ g, const float* __restrict__ b,
                              float* __restrict__ out, __half* __restrict__ out16) {
    int token = blockIdx.x * 8 + (threadIdx.x >> 5);
    int lane = threadIdx.x & 31;
    const float4* xr = (const float4*)(x + (size_t)token * DD);
    const float4* yr = (const float4*)(y + (size_t)token * DD);

    float4 v[4];
    float s = 0.f;
#pragma unroll
    for (int c = 0; c < 4; c++) {
        float4 a = xr[lane + 32*c];
        float4 w = yr[lane + 32*c];
        v[c].x = a.x + w.x; v[c].y = a.y + w.y;
        v[c].z = a.z + w.z; v[c].w = a.w + w.w;
        s += v[c].x + v[c].y + v[c].z + v[c].w;
    }
#pragma unroll
    for (int off = 16; off; off >>= 1) s += __shfl_xor_sync(0xffffffffu, s, off);
    float mu = s * (1.f / 512.f);

    float sq = 0.f;
#pragma unroll
    for (int c = 0; c < 4; c++) {
        float dx = v[c].x - mu, dy = v[c].y - mu, dz = v[c].z - mu, dw = v[c].w - mu;
        sq += dx*dx + dy*dy + dz*dz + dw*dw;
    }
#pragma unroll
    for (int off = 16; off; off >>= 1) sq += __shfl_xor_sync(0xffffffffu, sq, off);
    float r = rsqrtf(sq * (1.f / 512.f) + 1e-5f);

    const float4* g4 = (const float4*)g;
    const float4* b4 = (const float4*)b;
    float4* orow = (float4*)(out + (size_t)token * DD);
    __half2* o16 = (__half2*)(out16 + (size_t)token * DD);
#pragma unroll
    for (int c = 0; c < 4; c++) {
        int idx = lane + 32*c;
        float4 gg = g4[idx], bb = b4[idx];
        float4 o;
        o.x = (v[c].x - mu) * r * gg.x + bb.x;
        o.y = (v[c].y - mu) * r * gg.y + bb.y;
        o.z = (v[c].z - mu) * r * gg.z + bb.z;
        o.w = (v[c].w - mu) * r * gg.w + bb.w;
        orow[idx] = o;
        o16[idx*2 + 0] = __floats2half2_rn(o.x, o.y);
        o16[idx*2 + 1] = __floats2half2_rn(o.z, o.w);
    }
}

// ---------------------------------------------------------------------------
extern "C" void kernel_launch(void* const* d_in, const int* in_sizes, int n_in,
                              void* d_out, int out_size) {
    const int*   track_ids  = (const int*)  d_in[0];
    const int*   artist_ids = (const int*)  d_in[1];
    const float* track_emb  = (const float*)d_in[2];
    const float* artist_emb = (const float*)d_in[3];
    const float* pos_emb    = (const float*)d_in[4];
    const float* Wqkv       = (const float*)d_in[5];
    const float* bqkv       = (const float*)d_in[6];
    const float* Wff        = (const float*)d_in[7];
    const float* bff        = (const float*)d_in[8];
    const float* Wout       = (const float*)d_in[9];
    const float* bout       = (const float*)d_in[10];
    const float* g1         = (const float*)d_in[11];
    const float* b1         = (const float*)d_in[12];
    const float* g2         = (const float*)d_in[13];
    const float* b2         = (const float*)d_in[14];
    float* out = (float*)d_out;

    float *x, *y, *bp;
    __half *x16, *h16, *wt16, *qkv16;
    cudaGetSymbolAddress((void**)&x,     g_x);
    cudaGetSymbolAddress((void**)&x16,   g_x16);
    cudaGetSymbolAddress((void**)&qkv16, g_qkv16);
    cudaGetSymbolAddress((void**)&y,     g_y);
    cudaGetSymbolAddress((void**)&h16,   g_h16);
    cudaGetSymbolAddress((void**)&bp,    g_bp);
    cudaGetSymbolAddress((void**)&wt16,  g_wt16);

    __half* wqkv16 = wt16;
    __half* wff16  = wt16 + (size_t)LL * QKV_W;
    __half* wout16 = wff16 + (size_t)LL * FF_W;

    cudaFuncSetAttribute(gemm_h<0>, cudaFuncAttributeMaxDynamicSharedMemorySize, GEMM_SMEM);
    cudaFuncSetAttribute(gemm_h<1>, cudaFuncAttributeMaxDynamicSharedMemorySize, GEMM_SMEM);
    cudaFuncSetAttribute(gemm_h<2>, cudaFuncAttributeMaxDynamicSharedMemorySize, GEMM_SMEM);
    cudaFuncSetAttribute(attn_kernel, cudaFuncAttributeMaxDynamicSharedMemorySize, ATT_SMEM);

    transpose_perm_h<<<dim3(DD/32, (3*DD)/32, LL), dim3(32, 8)>>>(Wqkv, bqkv);
    transpose_h<<<dim3(DD/32, DFF/32, LL), dim3(32, 8)>>>(Wff, wff16, DD, DFF);
    transpose_h<<<dim3(DFF/32, DD/32, LL), dim3(32, 8)>>>(Wout, wout16, DFF, DD);

    embed_kernel<<<NTOK, 128>>>(track_ids, artist_ids, track_emb, artist_emb, pos_emb);

    for (int i = 0; i < LL; i++) {
        gemm_h<2><<<dim3((3*DD)/128, NTOK/256), 256, GEMM_SMEM>>>(
            x16, wqkv16 + (size_t)i * QKV_W, bp + (size_t)i * 3*DD, qkv16, 3*DD, DD);
        attn_kernel<<<dim3(BB*HH, 4), 256, ATT_SMEM>>>(qkv16, track_ids, y);
        add_ln_kernel<<<NTOK/8, 256>>>(x, y, g1 + (size_t)i*DD, b1 + (size_t)i*DD, x, x16);
        gemm_h<1><<<dim3(DFF/128, NTOK/256), 256, GEMM_SMEM>>>(
            x16, wff16 + (size_t)i * FF_W, bff + (size_t)i * DFF, h16, DFF, DD);
        gemm_h<0><<<dim3(DD/128, NTOK/256), 256, GEMM_SMEM>>>(
            h16, wout16 + (size_t)i * FF_W, bout + (size_t)i * DD, y, DD, DFF);
        add_ln_kernel<<<NTOK/8, 256>>>(x, y, g2 + (size_t)i*DD, b2 + (size_t)i*DD,
                                       (i == LL-1) ? out : x, x16);
    }
}